// round 13
// baseline (speedup 1.0000x reference)
#include <cuda_runtime.h>
#include <cuda_bf16.h>
#include <cstdint>

#define S_TOT 2112          // 64 mem + 2048 tokens
#define MEMN  64
#define DIM   768
#define HID   3072
#define NHEAD 12
#define HD    64
#define NLAYER 4
#define QKVN  (3 * DIM)     // 2304

// ---------------- scratch (device globals; no allocation allowed) ----------
__device__ __align__(16) float g_X [S_TOT * DIM];

__device__ __align__(16) __nv_bfloat16 g_Nh[S_TOT * DIM];
__device__ __align__(16) __nv_bfloat16 g_Nl[S_TOT * DIM];
__device__ __align__(16) __nv_bfloat16 g_QKVh[S_TOT * QKVN];
__device__ __align__(16) __nv_bfloat16 g_QKVl[S_TOT * QKVN];
__device__ __align__(16) __nv_bfloat16 g_Ahp[S_TOT * DIM];
__device__ __align__(16) __nv_bfloat16 g_Alp[S_TOT * DIM];
__device__ __align__(16) __nv_bfloat16 g_Fh[S_TOT * HID];
__device__ __align__(16) __nv_bfloat16 g_Fl[S_TOT * HID];

// preconverted weights (hi/lo bf16), all layers
#define WSZ_P   (NLAYER * DIM * DIM)
#define WSZ_FF  (NLAYER * HID * DIM)
#define OFF_QKV 0
#define OFF_WO  (OFF_QKV + 3 * WSZ_P)
#define OFF_W1  (OFF_WO + WSZ_P)
#define OFF_W2  (OFF_W1 + WSZ_FF)
#define WTOT    (OFF_W2 + WSZ_FF)
__device__ __align__(16) __nv_bfloat16 g_Wh[WTOT];
__device__ __align__(16) __nv_bfloat16 g_Wl[WTOT];

// =================== helpers ================================================
__device__ __forceinline__ uint32_t smem_u32(const void* p) {
    uint32_t a;
    asm("{ .reg .u64 t; cvta.to.shared.u64 t, %1; cvt.u32.u64 %0, t; }"
        : "=r"(a) : "l"(p));
    return a;
}
__device__ __forceinline__ void ldsm_x4(uint32_t* r, uint32_t addr) {
    asm volatile("ldmatrix.sync.aligned.m8n8.x4.shared.b16 {%0,%1,%2,%3}, [%4];"
                 : "=r"(r[0]), "=r"(r[1]), "=r"(r[2]), "=r"(r[3]) : "r"(addr));
}
__device__ __forceinline__ void ldsm_x4t(uint32_t* r, uint32_t addr) {
    asm volatile("ldmatrix.sync.aligned.m8n8.x4.trans.shared.b16 {%0,%1,%2,%3}, [%4];"
                 : "=r"(r[0]), "=r"(r[1]), "=r"(r[2]), "=r"(r[3]) : "r"(addr));
}
__device__ __forceinline__ void mma16816(float* c, const uint32_t* a,
                                         const uint32_t b0, const uint32_t b1) {
    asm volatile("mma.sync.aligned.m16n8k16.row.col.f32.bf16.bf16.f32 "
                 "{%0,%1,%2,%3}, {%4,%5,%6,%7}, {%8,%9}, {%0,%1,%2,%3};"
                 : "+f"(c[0]), "+f"(c[1]), "+f"(c[2]), "+f"(c[3])
                 : "r"(a[0]), "r"(a[1]), "r"(a[2]), "r"(a[3]), "r"(b0), "r"(b1));
}
__device__ __forceinline__ void cp_async16(uint32_t dst, const void* src, bool pred) {
    int sz = pred ? 16 : 0;
    asm volatile("cp.async.cg.shared.global [%0], [%1], 16, %2;"
                 :: "r"(dst), "l"(src), "r"(sz) : "memory");
}
#define CP_COMMIT() asm volatile("cp.async.commit_group;" ::: "memory")
#define CP_WAIT1()  asm volatile("cp.async.wait_group 1;" ::: "memory")
#define CP_WAIT0()  asm volatile("cp.async.wait_group 0;" ::: "memory")

// XOR chunk swizzle: 64B rows, 4 chunks of 16B; conflict-free for ldmatrix.
__device__ __forceinline__ uint32_t swz(int row, int chunk) {
    return (uint32_t)(row * 64 + ((chunk ^ ((row >> 1) & 3)) << 4));
}

__device__ __forceinline__ void split4(float4 v, uint2& hi, uint2& lo)
{
    __nv_bfloat16 h0 = __float2bfloat16(v.x);
    __nv_bfloat16 h1 = __float2bfloat16(v.y);
    __nv_bfloat16 h2 = __float2bfloat16(v.z);
    __nv_bfloat16 h3 = __float2bfloat16(v.w);
    __nv_bfloat16 l0 = __float2bfloat16(v.x - __bfloat162float(h0));
    __nv_bfloat16 l1 = __float2bfloat16(v.y - __bfloat162float(h1));
    __nv_bfloat16 l2 = __float2bfloat16(v.z - __bfloat162float(h2));
    __nv_bfloat16 l3 = __float2bfloat16(v.w - __bfloat162float(h3));
    hi.x = (uint32_t)__bfloat16_as_ushort(h1) << 16 | __bfloat16_as_ushort(h0);
    hi.y = (uint32_t)__bfloat16_as_ushort(h3) << 16 | __bfloat16_as_ushort(h2);
    lo.x = (uint32_t)__bfloat16_as_ushort(l1) << 16 | __bfloat16_as_ushort(l0);
    lo.y = (uint32_t)__bfloat16_as_ushort(l3) << 16 | __bfloat16_as_ushort(l2);
}
__device__ __forceinline__ void split2(float a, float b, uint32_t& hi, uint32_t& lo)
{
    __nv_bfloat16 ha = __float2bfloat16(a), hb = __float2bfloat16(b);
    __nv_bfloat16 la = __float2bfloat16(a - __bfloat162float(ha));
    __nv_bfloat16 lb = __float2bfloat16(b - __bfloat162float(hb));
    hi = (uint32_t)__bfloat16_as_ushort(hb) << 16 | __bfloat16_as_ushort(ha);
    lo = (uint32_t)__bfloat16_as_ushort(lb) << 16 | __bfloat16_as_ushort(la);
}

// ---------------- unified weight pre-conversion (1 launch) ------------------
#define N4_QKV (3 * WSZ_P / 4)
#define N4_WO  (WSZ_P / 4)
#define N4_FF  (WSZ_FF / 4)
#define N4_TOT (N4_QKV + N4_WO + 2 * N4_FF)

__global__ void conv_all(const float* __restrict__ wq, const float* __restrict__ wk,
                         const float* __restrict__ wv, const float* __restrict__ wo,
                         const float* __restrict__ w1, const float* __restrict__ w2,
                         __nv_bfloat16* __restrict__ Wh, __nv_bfloat16* __restrict__ Wl)
{
    int i = blockIdx.x * 256 + threadIdx.x;
    if (i >= N4_TOT) return;
    const float* src;
    size_t se, de;
    if (i < N4_QKV) {
        const int n4l = DIM * DIM / 4;
        const int per_t = NLAYER * n4l;
        int t = i / per_t;
        int r = i - t * per_t;
        int l = r / n4l, e = r - l * n4l;
        src = (t == 0) ? wq : (t == 1) ? wk : wv;
        se = (size_t)l * n4l + e;
        de = (size_t)(OFF_QKV / 4) + (size_t)l * (3 * n4l) + (size_t)t * n4l + e;
    } else if (i < N4_QKV + N4_WO) {
        int e = i - N4_QKV;
        src = wo; se = e; de = OFF_WO / 4 + e;
    } else if (i < N4_QKV + N4_WO + N4_FF) {
        int e = i - N4_QKV - N4_WO;
        src = w1; se = e; de = OFF_W1 / 4 + e;
    } else {
        int e = i - N4_QKV - N4_WO - N4_FF;
        src = w2; se = e; de = OFF_W2 / 4 + e;
    }
    float4 v = ((const float4*)src)[se];
    uint2 hi, lo;
    split4(v, hi, lo);
    ((uint2*)Wh)[de] = hi;
    ((uint2*)Wl)[de] = lo;
}

// ---------------- embedding ------------------------------------------------
__global__ void embed_kernel(const int* __restrict__ tokens,
                             const float* __restrict__ emb,
                             const float* __restrict__ pos,
                             const float* __restrict__ mem,
                             float* __restrict__ X)
{
    int idx = blockIdx.x * 256 + threadIdx.x;
    if (idx >= S_TOT * DIM) return;
    int s = idx / DIM;
    int d = idx - s * DIM;
    if (s < MEMN) {
        X[idx] = mem[s * DIM + d];
    } else {
        int t = s - MEMN;
        X[idx] = emb[tokens[t] * DIM + d] + pos[t * DIM + d];
    }
}

// ---------------- layernorm (384 threads, float2 per thread) ----------------
__device__ __forceinline__ void ln_stats384(float a, float b, float& mean, float& inv)
{
    int t = threadIdx.x;
    float s = a + b;
    float q = a * a + b * b;
#pragma unroll
    for (int off = 16; off; off >>= 1) {
        s += __shfl_xor_sync(0xffffffffu, s, off);
        q += __shfl_xor_sync(0xffffffffu, q, off);
    }
    __shared__ float rs[12], rq[12];
    __shared__ float mean_sh, inv_sh;
    int w = t >> 5;
    if ((t & 31) == 0) { rs[w] = s; rq[w] = q; }
    __syncthreads();
    if (t == 0) {
        float S = 0.f, Q = 0.f;
#pragma unroll
        for (int i = 0; i < 12; i++) { S += rs[i]; Q += rq[i]; }
        float mn = S * (1.0f / DIM);
        float var = Q * (1.0f / DIM) - mn * mn;
        mean_sh = mn;
        inv_sh  = rsqrtf(var + 1e-5f);
    }
    __syncthreads();
    mean = mean_sh;
    inv  = inv_sh;
}

__global__ void ln_hl_kernel(const float* __restrict__ X,
                             const float* __restrict__ g,
                             const float* __restrict__ bt,
                             __nv_bfloat16* __restrict__ oh,
                             __nv_bfloat16* __restrict__ ol)
{
    int row = blockIdx.x;
    int t = threadIdx.x;
    float2 v = ((const float2*)(X + (size_t)row * DIM))[t];
    float mean, inv;
    ln_stats384(v.x, v.y, mean, inv);
    float2 gv = ((const float2*)g)[t];
    float2 bv = ((const float2*)bt)[t];
    float y0 = (v.x - mean) * inv * gv.x + bv.x;
    float y1 = (v.y - mean) * inv * gv.y + bv.y;
    uint32_t hi, lo;
    split2(y0, y1, hi, lo);
    ((uint32_t*)oh)[(size_t)row * (DIM / 2) + t] = hi;
    ((uint32_t*)ol)[(size_t)row * (DIM / 2) + t] = lo;
}

__global__ void ln_kernel(const float* __restrict__ X,
                          const float* __restrict__ g,
                          const float* __restrict__ bt,
                          float* __restrict__ out, int in_off)
{
    int row = blockIdx.x + in_off;
    int t = threadIdx.x;
    float2 v = ((const float2*)(X + (size_t)row * DIM))[t];
    float mean, inv;
    ln_stats384(v.x, v.y, mean, inv);
    float2 gv = ((const float2*)g)[t];
    float2 bv = ((const float2*)bt)[t];
    float y0 = (v.x - mean) * inv * gv.x + bv.x;
    float y1 = (v.y - mean) * inv * gv.y + bv.y;
    ((float2*)(out + (size_t)blockIdx.x * DIM))[t] = make_float2(y0, y1);
}

__device__ __forceinline__ float gelu_tanh(float x)
{
    const float c = 0.7978845608028654f;
    float u = c * (x + 0.044715f * x * x * x);
    return 0.5f * x * (1.0f + tanhf(u));
}

// =================== bf16x3 GEMM, CTA BMx128, 3-stage swizzled, 2 CTAs/SM ===
#define BMATB  8192                  // B: 128 rows x 64B

template <int BM>
struct GemmDims {
    static const int AMATB = BM * 64;                 // A: BM rows x 64B
    static const int STG   = 2 * AMATB + 2 * BMATB;
    static const int SMEM  = 3 * STG;                 // 3 stages
    static const int MT    = BM / 32;
};

template <int BM, bool GELU, bool RES, bool BIAS, bool OUTHL>
__global__ __launch_bounds__(256, 2)
void gemm_tc(const __nv_bfloat16* __restrict__ Ah, const __nv_bfloat16* __restrict__ Al,
             const __nv_bfloat16* __restrict__ Bh, const __nv_bfloat16* __restrict__ Bl,
             const float* __restrict__ bias, const float* __restrict__ resid,
             float* __restrict__ C,
             __nv_bfloat16* __restrict__ Oh, __nv_bfloat16* __restrict__ Ol,
             int Mr, int N, int K)
{
    typedef GemmDims<BM> D;
    extern __shared__ char smem[];
    const uint32_t sb = smem_u32(smem);
    const int tid = threadIdx.x, wid = tid >> 5, lane = tid & 31;
    const int bm = blockIdx.y, bn = blockIdx.x;
    const int wm = (wid >> 2) * (BM / 2);
    const int wn = (wid & 3) * 32;
    const int KT = K >> 5;

    float acc[D::MT][4][4];
#pragma unroll
    for (int i = 0; i < D::MT; i++)
#pragma unroll
        for (int j = 0; j < 4; j++)
#pragma unroll
            for (int k = 0; k < 4; k++) acc[i][j][k] = 0.f;

    auto issue = [&](int kt) {
        const uint32_t stg = sb + (kt % 3) * D::STG;
        const int kb = kt * 32;
#pragma unroll
        for (int i = 0; i < BM / 64; i++) {
            int e = tid + i * 256;
            int row = e >> 2, kc = e & 3;
            uint32_t d = stg + swz(row, kc);
            int ga = bm * BM + row;
            const bool av = ga < Mr;
            if (!av) ga = 0;
            const size_t aoff = (size_t)ga * K + kb + kc * 8;
            cp_async16(d,            Ah + aoff, av);
            cp_async16(d + D::AMATB, Al + aoff, av);
        }
#pragma unroll
        for (int i = 0; i < 2; i++) {
            int e = tid + i * 256;
            int row = e >> 2, kc = e & 3;
            uint32_t d = stg + 2 * D::AMATB + swz(row, kc);
            const size_t boff = (size_t)(bn * 128 + row) * K + kb + kc * 8;
            cp_async16(d,         Bh + boff, true);
            cp_async16(d + BMATB, Bl + boff, true);
        }
        CP_COMMIT();
    };

    issue(0);
    if (KT > 1) issue(1);

    const int arow = wm + (lane & 15);
    const int acO  = (lane >> 4) << 3;
    const int brow = wn + (lane & 7) + ((lane >> 4) << 3);
    const int bcO  = ((lane >> 3) & 1) << 3;

    for (int kt = 0; kt < KT; kt++) {
        CP_WAIT1();
        __syncthreads();
        if (kt + 2 < KT) issue(kt + 2);

        const uint32_t base = sb + (kt % 3) * D::STG;
#pragma unroll
        for (int ks = 0; ks < 2; ks++) {
            const int k0 = ks * 16;
            uint32_t aH[D::MT][4], aL[D::MT][4], bH[2][4], bL[2][4];
#pragma unroll
            for (int mt = 0; mt < D::MT; mt++) {
                const int r = arow + mt * 16;
                uint32_t ad = base + swz(r, (k0 + acO) >> 3);
                ldsm_x4(aH[mt], ad);
                ldsm_x4(aL[mt], ad + D::AMATB);
            }
#pragma unroll
            for (int n2 = 0; n2 < 2; n2++) {
                const int r = brow + n2 * 16;
                uint32_t bd = base + 2 * D::AMATB + swz(r, (k0 + bcO) >> 3);
                ldsm_x4(bH[n2], bd);
                ldsm_x4(bL[n2], bd + BMATB);
            }
#pragma unroll
            for (int mt = 0; mt < D::MT; mt++)
#pragma unroll
                for (int nt = 0; nt < 4; nt++) {
                    const int n2 = nt >> 1, hb = (nt & 1) * 2;
                    mma16816(acc[mt][nt], aH[mt], bH[n2][hb], bH[n2][hb + 1]);
                    mma16816(acc[mt][nt], aH[mt], bL[n2][hb], bL[n2][hb + 1]);
                    mma16816(acc[mt][nt], aL[mt], bH[n2][hb], bH[n2][hb + 1]);
                }
        }
    }

#pragma unroll
    for (int mt = 0; mt < D::MT; mt++) {
        const int r0 = bm * BM + wm + mt * 16 + (lane >> 2);
#pragma unroll
        for (int nt = 0; nt < 4; nt++) {
            const int col = bn * 128 + wn + nt * 8 + (lane & 3) * 2;
            float* c = acc[mt][nt];
            float bx = 0.f, by = 0.f;
            if (BIAS) { float2 bv = *(const float2*)(bias + col); bx = bv.x; by = bv.y; }
#pragma unroll
            for (int hh = 0; hh < 2; hh++) {
                const int r = r0 + hh * 8;
                if (r >= Mr) continue;
                float v0 = c[hh * 2 + 0], v1 = c[hh * 2 + 1];
                if (BIAS) { v0 += bx; v1 += by; }
                if (GELU) { v0 = gelu_tanh(v0); v1 = gelu_tanh(v1); }
                if (OUTHL) {
                    uint32_t hi, lo;
                    split2(v0, v1, hi, lo);
                    *(uint32_t*)(Oh + (size_t)r * N + col) = hi;
                    *(uint32_t*)(Ol + (size_t)r * N + col) = lo;
                } else {
                    if (RES) {
                        float2 rv = *(const float2*)(resid + (size_t)r * N + col);
                        v0 += rv.x; v1 += rv.y;
                    }
                    *(float2*)(C + (size_t)r * N + col) = make_float2(v0, v1);
                }
            }
        }
    }
}

// =================== tensor-core flash attention =============================
// 256 threads (8 warps), 128 queries per block; 2-stage KV pipeline.
// smem: Qh Ql (128x72 each) + 2 stages x {Kh Kl Vh Vl} (64x72 each).
#define APITCH 72
#define AQMATB (128 * APITCH * 2)    // 18432
#define AKMATB (64 * APITCH * 2)     // 9216
#define ATTN_SMEM (2 * AQMATB + 8 * AKMATB)   // 110592

__global__ __launch_bounds__(256, 1)
void attn_tc(const __nv_bfloat16* __restrict__ QKVh,
             const __nv_bfloat16* __restrict__ QKVl,
             __nv_bfloat16* __restrict__ Oh, __nv_bfloat16* __restrict__ Ol)
{
    extern __shared__ char asmem[];
    const uint32_t sb = smem_u32(asmem);
    const uint32_t oQh = 0, oQl = AQMATB;
    const uint32_t kvBase = 2 * AQMATB;
    const int qblk = gridDim.x - 1 - blockIdx.x;      // heavy blocks first
    const int h = blockIdx.y;
    const int tid = threadIdx.x, wid = tid >> 5, lane = tid & 31;
    const int wr = wid * 16;                           // warp query offset in block
    const int qbase = qblk * 128;
    const int kend = min(2 * qblk + 1, S_TOT / 64 - 1);

    // load Q (128 rows, clamped)
#pragma unroll
    for (int i = 0; i < 4; i++) {
        int idx = tid + i * 256;
        int row = idx >> 3, ch = idx & 7;
        int grow = qbase + row;
        if (grow >= S_TOT) grow = S_TOT - 1;
        size_t goff = (size_t)grow * QKVN + h * HD + ch * 8;
        uint32_t soff = row * (APITCH * 2) + ch * 16;
        cp_async16(sb + oQh + soff, QKVh + goff, true);
        cp_async16(sb + oQl + soff, QKVl + goff, true);
    }
    CP_COMMIT();

    auto issueKV = [&](int kb) {
        const uint32_t st = sb + kvBase + (kb & 1) * (4 * AKMATB);
#pragma unroll
        for (int i = 0; i < 2; i++) {
            int idx = tid + i * 256;
            int row = idx >> 3, ch = idx & 7;
            size_t gK = (size_t)(kb * 64 + row) * QKVN + DIM + h * HD + ch * 8;
            size_t gV = (size_t)(kb * 64 + row) * QKVN + 2 * DIM + h * HD + ch * 8;
            uint32_t soff = row * (APITCH * 2) + ch * 16;
            cp_async16(st + soff,              QKVh + gK, true);
            cp_async16(st + AKMATB + soff,     QKVl + gK, true);
            cp_async16(st + 2 * AKMATB + soff, QKVh + gV, true);
            cp_async16(st + 3 * AKMATB + soff, QKVl + gV, true);
        }
        CP_COMMIT();
    };

    issueKV(0);
    if (kend >= 1) issueKV(1);

    float m_[2] = {-1e30f, -1e30f}, l_[2] = {0.f, 0.f};
    float ov[8][4];
#pragma unroll
    for (int i = 0; i < 8; i++)
#pragma unroll
        for (int j = 0; j < 4; j++) ov[i][j] = 0.f;
    const float scale = 0.125f;

    const int ar = wr + (lane & 15);
    const int ac = (lane >> 4) << 3;
    const int br = (lane & 7) + ((lane >> 4) << 3);
    const int bc = ((lane >> 3) & 1) << 3;
    const int vrb = (lane & 7) + (((lane >> 3) & 1) << 3);
    const int vcb = (lane >> 4) << 3;
    const int lr0 = lane >> 2;
    const int lc0 = (lane & 3) * 2;

    for (int kb = 0; kb <= kend; kb++) {
        if (kb + 1 <= kend) { CP_WAIT1(); } else { CP_WAIT0(); }
        __syncthreads();

        const uint32_t st  = sb + kvBase + (kb & 1) * (4 * AKMATB);
        const uint32_t oKh = st, oKl = st + AKMATB;
        const uint32_t oVh = st + 2 * AKMATB, oVl = st + 3 * AKMATB;

        float sv[8][4];
#pragma unroll
        for (int i = 0; i < 8; i++)
#pragma unroll
            for (int j = 0; j < 4; j++) sv[i][j] = 0.f;

#pragma unroll
        for (int ks = 0; ks < 4; ks++) {
            uint32_t aH[4], aL[4];
            uint32_t ao = sb + (ar * APITCH + ks * 16 + ac) * 2;
            ldsm_x4(aH, ao + oQh);
            ldsm_x4(aL, ao + oQl);
#pragma unroll
            for (int g = 0; g < 4; g++) {
                uint32_t bH4[4], bL4[4];
                uint32_t bo = ((g * 16 + br) * APITCH + ks * 16 + bc) * 2;
                ldsm_x4(bH4, bo + oKh);
                ldsm_x4(bL4, bo + oKl);
                mma16816(sv[2 * g],     aH, bH4[0], bH4[1]);
                mma16816(sv[2 * g],     aH, bL4[0], bL4[1]);
                mma16816(sv[2 * g],     aL, bH4[0], bH4[1]);
                mma16816(sv[2 * g + 1], aH, bH4[2], bH4[3]);
                mma16816(sv[2 * g + 1], aH, bL4[2], bL4[3]);
                mma16816(sv[2 * g + 1], aL, bH4[2], bH4[3]);
            }
        }

        // scale + causal mask (global indices; only needed near diagonal)
        const bool diag = (kb >= 2 * qblk);
#pragma unroll
        for (int nt = 0; nt < 8; nt++)
#pragma unroll
            for (int e = 0; e < 4; e++) {
                float x = sv[nt][e] * scale;
                if (diag) {
                    int kcol = kb * 64 + nt * 8 + lc0 + (e & 1);
                    int qrow = qbase + wr + lr0 + ((e >> 1) << 3);
                    if (kcol > qrow) x = -1e30f;
                }
                sv[nt][e] = x;
            }

        float mx0 = -1e30f, mx1 = -1e30f;
#pragma unroll
        for (int nt = 0; nt < 8; nt++) {
            mx0 = fmaxf(mx0, fmaxf(sv[nt][0], sv[nt][1]));
            mx1 = fmaxf(mx1, fmaxf(sv[nt][2], sv[nt][3]));
        }
        mx0 = fmaxf(mx0, __shfl_xor_sync(0xffffffffu, mx0, 1));
        mx0 = fmaxf(mx0, __shfl_xor_sync(0xffffffffu, mx0, 2));
        mx1 = fmaxf(mx1, __shfl_xor_sync(0xffffffffu, mx1, 1));
        mx1 = fmaxf(mx1, __shfl_xor_sync(0xffffffffu, mx1, 2));
        float mn0 = fmaxf(m_[0], mx0), mn1 = fmaxf(m_[1], mx1);
        float cr0 = __expf(m_[0] - mn0), cr1 = __expf(m_[1] - mn1);
        float sum0 = 0.f, sum1 = 0.f;
#pragma unroll
        for (int nt = 0; nt < 8; nt++) {
            float p0 = __expf(sv[nt][0] - mn0);
            float p1 = __expf(sv[nt][1] - mn0);
            float p2 = __expf(sv[nt][2] - mn1);
            float p3 = __expf(sv[nt][3] - mn1);
            sv[nt][0] = p0; sv[nt][1] = p1; sv[nt][2] = p2; sv[nt][3] = p3;
            sum0 += p0 + p1;
            sum1 += p2 + p3;
        }
        sum0 += __shfl_xor_sync(0xffffffffu, sum0, 1);
        sum0 += __shfl_xor_sync(0xffffffffu, sum0, 2);
        sum1 += __shfl_xor_sync(0xffffffffu, sum1, 1);
        sum1 += __shfl_xor_sync(0xffffffffu, sum1, 2);
        l_[0] = l_[0] * cr0 + sum0;
        l_[1] = l_[1] * cr1 + sum1;
        m_[0] = mn0; m_[1] = mn1;
#pragma unroll
        for (int nt = 0; nt < 8; nt++) {
            ov[nt][0] *= cr0; ov[nt][1] *= cr0;
            ov[nt][2] *= cr1; ov[nt][3] *= cr1;
        }

#pragma unroll
        for (int s = 0; s < 4; s++) {
            uint32_t pH[4], pL[4];
            split2(sv[2 * s][0],     sv[2 * s][1],     pH[0], pL[0]);
            split2(sv[2 * s][2],     sv[2 * s][3],     pH[1], pL[1]);
            split2(sv[2 * s + 1][0], sv[2 * s + 1][1], pH[2], pL[2]);
            split2(sv[2 * s + 1][2], sv[2 * s + 1][3], pH[3], pL[3]);
            const int vrow = s * 16 + vrb;
#pragma unroll
            for (int g = 0; g < 4; g++) {
                uint32_t vH4[4], vL4[4];
                uint32_t vo = (vrow * APITCH + g * 16 + vcb) * 2;
                ldsm_x4t(vH4, vo + oVh);
                ldsm_x4t(vL4, vo + oVl);
                mma16816(ov[2 * g],     pH, vH4[0], vH4[1]);
                mma16816(ov[2 * g],     pH, vL4[0], vL4[1]);
                mma16816(ov[2 * g],     pL, vH4[0], vH4[1]);
                mma16816(ov[2 * g + 1], pH, vH4[2], vH4[3]);
                mma16816(ov[2 * g + 1], pH, vL4[2], vL4[3]);
                mma16816(ov[2 * g + 1], pL, vH4[2], vH4[3]);
            }
        }

        __syncthreads();
        if (kb + 2 <= kend) issueKV(kb + 2);
    }

    const float inv0 = 1.0f / l_[0], inv1 = 1.0f / l_[1];
    const int gr0 = qbase + wr + (lane >> 2);
    const int cb  = h * HD + (lane & 3) * 2;
#pragma unroll
    for (int nt = 0; nt < 8; nt++) {
        const int col = cb + nt * 8;
        uint32_t hi, lo;
        if (gr0 < S_TOT) {
            split2(ov[nt][0] * inv0, ov[nt][1] * inv0, hi, lo);
            *(uint32_t*)(Oh + (size_t)gr0 * DIM + col) = hi;
            *(uint32_t*)(Ol + (size_t)gr0 * DIM + col) = lo;
        }
        if (gr0 + 8 < S_TOT) {
            split2(ov[nt][2] * inv1, ov[nt][3] * inv1, hi, lo);
            *(uint32_t*)(Oh + (size_t)(gr0 + 8) * DIM + col) = hi;
            *(uint32_t*)(Ol + (size_t)(gr0 + 8) * DIM + col) = lo;
        }
    }
}

// ---------------- launch ----------------------------------------------------
extern "C" void kernel_launch(void* const* d_in, const int* in_sizes, int n_in,
                              void* d_out, int out_size)
{
    const int*   tokens = (const int*)  d_in[0];
    const float* emb    = (const float*)d_in[1];
    const float* pos    = (const float*)d_in[2];
    const float* mem    = (const float*)d_in[3];
    const float* ln1_s  = (const float*)d_in[4];
    const float* ln1_b  = (const float*)d_in[5];
    const float* wq     = (const float*)d_in[6];
    const float* wk     = (const float*)d_in[7];
    const float* wv     = (const float*)d_in[8];
    const float* wo     = (const float*)d_in[9];
    const float* ln2_s  = (const float*)d_in[10];
    const float* ln2_b  = (const float*)d_in[11];
    const float* w1     = (const float*)d_in[12];
    const float* b1     = (const float*)d_in[13];
    const float* w2     = (const float*)d_in[14];
    const float* b2     = (const float*)d_in[15];
    const float* lnm_s  = (const float*)d_in[16];
    const float* lnm_b  = (const float*)d_in[17];

    float *X;
    __nv_bfloat16 *Nh, *Nl, *QKVh, *QKVl, *Aoh, *Aol, *Fh, *Fl, *Wh, *Wl;
    cudaGetSymbolAddress((void**)&X,    g_X);
    cudaGetSymbolAddress((void**)&Nh,   g_Nh);
    cudaGetSymbolAddress((void**)&Nl,   g_Nl);
    cudaGetSymbolAddress((void**)&QKVh, g_QKVh);
    cudaGetSymbolAddress((void**)&QKVl, g_QKVl);
    cudaGetSymbolAddress((void**)&Aoh,  g_Ahp);
    cudaGetSymbolAddress((void**)&Aol,  g_Alp);
    cudaGetSymbolAddress((void**)&Fh,   g_Fh);
    cudaGetSymbolAddress((void**)&Fl,   g_Fl);
    cudaGetSymbolAddress((void**)&Wh,   g_Wh);
    cudaGetSymbolAddress((void**)&Wl,   g_Wl);

    const int SMEM128 = GemmDims<128>::SMEM;   // 98304
    const int SMEM64  = GemmDims<64>::SMEM;    // 73728

    cudaFuncSetAttribute(attn_tc, cudaFuncAttributeMaxDynamicSharedMemorySize, ATTN_SMEM);
    cudaFuncSetAttribute(gemm_tc<128, false, false, false, true >, cudaFuncAttributeMaxDynamicSharedMemorySize, SMEM128);
    cudaFuncSetAttribute(gemm_tc<128, true,  false, true,  true >, cudaFuncAttributeMaxDynamicSharedMemorySize, SMEM128);
    cudaFuncSetAttribute(gemm_tc<64,  false, true,  false, false>, cudaFuncAttributeMaxDynamicSharedMemorySize, SMEM64);
    cudaFuncSetAttribute(gemm_tc<64,  false, true,  true,  false>, cudaFuncAttributeMaxDynamicSharedMemorySize, SMEM64);

    conv_all<<<(N4_TOT + 255) / 256, 256>>>(wq, wk, wv, wo, w1, w2, Wh, Wl);
    embed_kernel<<<(S_TOT * DIM + 255) / 256, 256>>>(tokens, emb, pos, mem, X);

    const dim3 gQKV(QKVN / 128, (S_TOT + 127) / 128);   // (18, 17)
    const dim3 gFF1 (HID / 128, (S_TOT + 127) / 128);   // (24, 17)
    const dim3 gP64 (DIM / 128, S_TOT / 64);            // (6, 33)
    const dim3 gATT ((S_TOT + 127) / 128, NHEAD);       // (17, 12)

    for (int l = 0; l < NLAYER; l++) {
        ln_hl_kernel<<<S_TOT, 384>>>(X, ln1_s + l * DIM, ln1_b + l * DIM, Nh, Nl);

        gemm_tc<128, false, false, false, true><<<gQKV, 256, SMEM128>>>(
            Nh, Nl,
            Wh + OFF_QKV + (size_t)l * 3 * DIM * DIM, Wl + OFF_QKV + (size_t)l * 3 * DIM * DIM,
            nullptr, nullptr, nullptr, QKVh, QKVl, S_TOT, QKVN, DIM);

        attn_tc<<<gATT, 256, ATTN_SMEM>>>(QKVh, QKVl, Aoh, Aol);

        gemm_tc<64, false, true, false, false><<<gP64, 256, SMEM64>>>(
            Aoh, Aol, Wh + OFF_WO + (size_t)l * DIM * DIM, Wl + OFF_WO + (size_t)l * DIM * DIM,
            nullptr, X, X, nullptr, nullptr, S_TOT, DIM, DIM);

        ln_hl_kernel<<<S_TOT, 384>>>(X, ln2_s + l * DIM, ln2_b + l * DIM, Nh, Nl);

        gemm_tc<128, true, false, true, true><<<gFF1, 256, SMEM128>>>(
            Nh, Nl, Wh + OFF_W1 + (size_t)l * HID * DIM, Wl + OFF_W1 + (size_t)l * HID * DIM,
            b1 + l * HID, nullptr, nullptr, Fh, Fl, S_TOT, HID, DIM);

        gemm_tc<64, false, true, true, false><<<gP64, 256, SMEM64>>>(
            Fh, Fl, Wh + OFF_W2 + (size_t)l * DIM * HID, Wl + OFF_W2 + (size_t)l * DIM * HID,
            b2 + l * DIM, X, X, nullptr, nullptr, S_TOT, DIM, HID);
    }

    ln_kernel<<<MEMN, 384>>>(X, lnm_s, lnm_b, (float*)d_out, S_TOT - MEMN);
}

// round 14
// speedup vs baseline: 1.0165x; 1.0165x over previous
#include <cuda_runtime.h>
#include <cuda_bf16.h>
#include <cstdint>

#define S_TOT 2112          // 64 mem + 2048 tokens
#define MEMN  64
#define DIM   768
#define HID   3072
#define NHEAD 12
#define HD    64
#define NLAYER 4
#define QKVN  (3 * DIM)     // 2304

// ---------------- scratch (device globals; no allocation allowed) ----------
__device__ __align__(16) float g_X [S_TOT * DIM];

__device__ __align__(16) __nv_bfloat16 g_Nh[S_TOT * DIM];
__device__ __align__(16) __nv_bfloat16 g_Nl[S_TOT * DIM];
__device__ __align__(16) __nv_bfloat16 g_QKVh[S_TOT * QKVN];
__device__ __align__(16) __nv_bfloat16 g_QKVl[S_TOT * QKVN];
__device__ __align__(16) __nv_bfloat16 g_Ahp[S_TOT * DIM];
__device__ __align__(16) __nv_bfloat16 g_Alp[S_TOT * DIM];
__device__ __align__(16) __nv_bfloat16 g_Fh[S_TOT * HID];
__device__ __align__(16) __nv_bfloat16 g_Fl[S_TOT * HID];

// preconverted weights (hi/lo bf16), all layers
#define WSZ_P   (NLAYER * DIM * DIM)
#define WSZ_FF  (NLAYER * HID * DIM)
#define OFF_QKV 0
#define OFF_WO  (OFF_QKV + 3 * WSZ_P)
#define OFF_W1  (OFF_WO + WSZ_P)
#define OFF_W2  (OFF_W1 + WSZ_FF)
#define WTOT    (OFF_W2 + WSZ_FF)
__device__ __align__(16) __nv_bfloat16 g_Wh[WTOT];
__device__ __align__(16) __nv_bfloat16 g_Wl[WTOT];

// =================== helpers ================================================
__device__ __forceinline__ uint32_t smem_u32(const void* p) {
    uint32_t a;
    asm("{ .reg .u64 t; cvta.to.shared.u64 t, %1; cvt.u32.u64 %0, t; }"
        : "=r"(a) : "l"(p));
    return a;
}
__device__ __forceinline__ void ldsm_x4(uint32_t* r, uint32_t addr) {
    asm volatile("ldmatrix.sync.aligned.m8n8.x4.shared.b16 {%0,%1,%2,%3}, [%4];"
                 : "=r"(r[0]), "=r"(r[1]), "=r"(r[2]), "=r"(r[3]) : "r"(addr));
}
__device__ __forceinline__ void ldsm_x4t(uint32_t* r, uint32_t addr) {
    asm volatile("ldmatrix.sync.aligned.m8n8.x4.trans.shared.b16 {%0,%1,%2,%3}, [%4];"
                 : "=r"(r[0]), "=r"(r[1]), "=r"(r[2]), "=r"(r[3]) : "r"(addr));
}
__device__ __forceinline__ void mma16816(float* c, const uint32_t* a,
                                         const uint32_t b0, const uint32_t b1) {
    asm volatile("mma.sync.aligned.m16n8k16.row.col.f32.bf16.bf16.f32 "
                 "{%0,%1,%2,%3}, {%4,%5,%6,%7}, {%8,%9}, {%0,%1,%2,%3};"
                 : "+f"(c[0]), "+f"(c[1]), "+f"(c[2]), "+f"(c[3])
                 : "r"(a[0]), "r"(a[1]), "r"(a[2]), "r"(a[3]), "r"(b0), "r"(b1));
}
__device__ __forceinline__ void cp_async16(uint32_t dst, const void* src, bool pred) {
    int sz = pred ? 16 : 0;
    asm volatile("cp.async.cg.shared.global [%0], [%1], 16, %2;"
                 :: "r"(dst), "l"(src), "r"(sz) : "memory");
}
#define CP_COMMIT() asm volatile("cp.async.commit_group;" ::: "memory")
#define CP_WAIT1()  asm volatile("cp.async.wait_group 1;" ::: "memory")
#define CP_WAIT0()  asm volatile("cp.async.wait_group 0;" ::: "memory")

// XOR chunk swizzle: 64B rows, 4 chunks of 16B; conflict-free for ldmatrix.
__device__ __forceinline__ uint32_t swz(int row, int chunk) {
    return (uint32_t)(row * 64 + ((chunk ^ ((row >> 1) & 3)) << 4));
}

__device__ __forceinline__ void split4(float4 v, uint2& hi, uint2& lo)
{
    __nv_bfloat16 h0 = __float2bfloat16(v.x);
    __nv_bfloat16 h1 = __float2bfloat16(v.y);
    __nv_bfloat16 h2 = __float2bfloat16(v.z);
    __nv_bfloat16 h3 = __float2bfloat16(v.w);
    __nv_bfloat16 l0 = __float2bfloat16(v.x - __bfloat162float(h0));
    __nv_bfloat16 l1 = __float2bfloat16(v.y - __bfloat162float(h1));
    __nv_bfloat16 l2 = __float2bfloat16(v.z - __bfloat162float(h2));
    __nv_bfloat16 l3 = __float2bfloat16(v.w - __bfloat162float(h3));
    hi.x = (uint32_t)__bfloat16_as_ushort(h1) << 16 | __bfloat16_as_ushort(h0);
    hi.y = (uint32_t)__bfloat16_as_ushort(h3) << 16 | __bfloat16_as_ushort(h2);
    lo.x = (uint32_t)__bfloat16_as_ushort(l1) << 16 | __bfloat16_as_ushort(l0);
    lo.y = (uint32_t)__bfloat16_as_ushort(l3) << 16 | __bfloat16_as_ushort(l2);
}
__device__ __forceinline__ void split2(float a, float b, uint32_t& hi, uint32_t& lo)
{
    __nv_bfloat16 ha = __float2bfloat16(a), hb = __float2bfloat16(b);
    __nv_bfloat16 la = __float2bfloat16(a - __bfloat162float(ha));
    __nv_bfloat16 lb = __float2bfloat16(b - __bfloat162float(hb));
    hi = (uint32_t)__bfloat16_as_ushort(hb) << 16 | __bfloat16_as_ushort(ha);
    lo = (uint32_t)__bfloat16_as_ushort(lb) << 16 | __bfloat16_as_ushort(la);
}

// ---------------- unified weight pre-conversion (1 launch) ------------------
#define N4_QKV (3 * WSZ_P / 4)
#define N4_WO  (WSZ_P / 4)
#define N4_FF  (WSZ_FF / 4)
#define N4_TOT (N4_QKV + N4_WO + 2 * N4_FF)

__global__ void conv_all(const float* __restrict__ wq, const float* __restrict__ wk,
                         const float* __restrict__ wv, const float* __restrict__ wo,
                         const float* __restrict__ w1, const float* __restrict__ w2,
                         __nv_bfloat16* __restrict__ Wh, __nv_bfloat16* __restrict__ Wl)
{
    int i = blockIdx.x * 256 + threadIdx.x;
    if (i >= N4_TOT) return;
    const float* src;
    size_t se, de;
    if (i < N4_QKV) {
        const int n4l = DIM * DIM / 4;
        const int per_t = NLAYER * n4l;
        int t = i / per_t;
        int r = i - t * per_t;
        int l = r / n4l, e = r - l * n4l;
        src = (t == 0) ? wq : (t == 1) ? wk : wv;
        se = (size_t)l * n4l + e;
        de = (size_t)(OFF_QKV / 4) + (size_t)l * (3 * n4l) + (size_t)t * n4l + e;
    } else if (i < N4_QKV + N4_WO) {
        int e = i - N4_QKV;
        src = wo; se = e; de = OFF_WO / 4 + e;
    } else if (i < N4_QKV + N4_WO + N4_FF) {
        int e = i - N4_QKV - N4_WO;
        src = w1; se = e; de = OFF_W1 / 4 + e;
    } else {
        int e = i - N4_QKV - N4_WO - N4_FF;
        src = w2; se = e; de = OFF_W2 / 4 + e;
    }
    float4 v = ((const float4*)src)[se];
    uint2 hi, lo;
    split4(v, hi, lo);
    ((uint2*)Wh)[de] = hi;
    ((uint2*)Wl)[de] = lo;
}

// ---------------- embedding ------------------------------------------------
__global__ void embed_kernel(const int* __restrict__ tokens,
                             const float* __restrict__ emb,
                             const float* __restrict__ pos,
                             const float* __restrict__ mem,
                             float* __restrict__ X)
{
    int idx = blockIdx.x * 256 + threadIdx.x;
    if (idx >= S_TOT * DIM) return;
    int s = idx / DIM;
    int d = idx - s * DIM;
    if (s < MEMN) {
        X[idx] = mem[s * DIM + d];
    } else {
        int t = s - MEMN;
        X[idx] = emb[tokens[t] * DIM + d] + pos[t * DIM + d];
    }
}

// ---------------- layernorm (384 threads, float2 per thread) ----------------
__device__ __forceinline__ void ln_stats384(float a, float b, float& mean, float& inv)
{
    int t = threadIdx.x;
    float s = a + b;
    float q = a * a + b * b;
#pragma unroll
    for (int off = 16; off; off >>= 1) {
        s += __shfl_xor_sync(0xffffffffu, s, off);
        q += __shfl_xor_sync(0xffffffffu, q, off);
    }
    __shared__ float rs[12], rq[12];
    __shared__ float mean_sh, inv_sh;
    int w = t >> 5;
    if ((t & 31) == 0) { rs[w] = s; rq[w] = q; }
    __syncthreads();
    if (t == 0) {
        float S = 0.f, Q = 0.f;
#pragma unroll
        for (int i = 0; i < 12; i++) { S += rs[i]; Q += rq[i]; }
        float mn = S * (1.0f / DIM);
        float var = Q * (1.0f / DIM) - mn * mn;
        mean_sh = mn;
        inv_sh  = rsqrtf(var + 1e-5f);
    }
    __syncthreads();
    mean = mean_sh;
    inv  = inv_sh;
}

__global__ void ln_hl_kernel(const float* __restrict__ X,
                             const float* __restrict__ g,
                             const float* __restrict__ bt,
                             __nv_bfloat16* __restrict__ oh,
                             __nv_bfloat16* __restrict__ ol)
{
    int row = blockIdx.x;
    int t = threadIdx.x;
    float2 v = ((const float2*)(X + (size_t)row * DIM))[t];
    float mean, inv;
    ln_stats384(v.x, v.y, mean, inv);
    float2 gv = ((const float2*)g)[t];
    float2 bv = ((const float2*)bt)[t];
    float y0 = (v.x - mean) * inv * gv.x + bv.x;
    float y1 = (v.y - mean) * inv * gv.y + bv.y;
    uint32_t hi, lo;
    split2(y0, y1, hi, lo);
    ((uint32_t*)oh)[(size_t)row * (DIM / 2) + t] = hi;
    ((uint32_t*)ol)[(size_t)row * (DIM / 2) + t] = lo;
}

__global__ void ln_kernel(const float* __restrict__ X,
                          const float* __restrict__ g,
                          const float* __restrict__ bt,
                          float* __restrict__ out, int in_off)
{
    int row = blockIdx.x + in_off;
    int t = threadIdx.x;
    float2 v = ((const float2*)(X + (size_t)row * DIM))[t];
    float mean, inv;
    ln_stats384(v.x, v.y, mean, inv);
    float2 gv = ((const float2*)g)[t];
    float2 bv = ((const float2*)bt)[t];
    float y0 = (v.x - mean) * inv * gv.x + bv.x;
    float y1 = (v.y - mean) * inv * gv.y + bv.y;
    ((float2*)(out + (size_t)blockIdx.x * DIM))[t] = make_float2(y0, y1);
}

__device__ __forceinline__ float gelu_tanh(float x)
{
    const float c = 0.7978845608028654f;
    float u = c * (x + 0.044715f * x * x * x);
    return 0.5f * x * (1.0f + tanhf(u));
}

// =================== bf16x3 GEMM, CTA BMx128, 3-stage swizzled, 2 CTAs/SM ===
#define BMATB  8192                  // B: 128 rows x 64B

template <int BM>
struct GemmDims {
    static const int AMATB = BM * 64;                 // A: BM rows x 64B
    static const int STG   = 2 * AMATB + 2 * BMATB;
    static const int SMEM  = 3 * STG;                 // 3 stages
    static const int MT    = BM / 32;
};

template <int BM, bool GELU, bool RES, bool BIAS, bool OUTHL>
__global__ __launch_bounds__(256, 2)
void gemm_tc(const __nv_bfloat16* __restrict__ Ah, const __nv_bfloat16* __restrict__ Al,
             const __nv_bfloat16* __restrict__ Bh, const __nv_bfloat16* __restrict__ Bl,
             const float* __restrict__ bias, const float* __restrict__ resid,
             float* __restrict__ C,
             __nv_bfloat16* __restrict__ Oh, __nv_bfloat16* __restrict__ Ol,
             int Mr, int N, int K)
{
    typedef GemmDims<BM> D;
    extern __shared__ char smem[];
    const uint32_t sb = smem_u32(smem);
    const int tid = threadIdx.x, wid = tid >> 5, lane = tid & 31;
    const int bm = blockIdx.y, bn = blockIdx.x;
    const int wm = (wid >> 2) * (BM / 2);
    const int wn = (wid & 3) * 32;
    const int KT = K >> 5;

    float acc[D::MT][4][4];
#pragma unroll
    for (int i = 0; i < D::MT; i++)
#pragma unroll
        for (int j = 0; j < 4; j++)
#pragma unroll
            for (int k = 0; k < 4; k++) acc[i][j][k] = 0.f;

    auto issue = [&](int kt) {
        const uint32_t stg = sb + (kt % 3) * D::STG;
        const int kb = kt * 32;
#pragma unroll
        for (int i = 0; i < BM / 64; i++) {
            int e = tid + i * 256;
            int row = e >> 2, kc = e & 3;
            uint32_t d = stg + swz(row, kc);
            int ga = bm * BM + row;
            const bool av = ga < Mr;
            if (!av) ga = 0;
            const size_t aoff = (size_t)ga * K + kb + kc * 8;
            cp_async16(d,            Ah + aoff, av);
            cp_async16(d + D::AMATB, Al + aoff, av);
        }
#pragma unroll
        for (int i = 0; i < 2; i++) {
            int e = tid + i * 256;
            int row = e >> 2, kc = e & 3;
            uint32_t d = stg + 2 * D::AMATB + swz(row, kc);
            const size_t boff = (size_t)(bn * 128 + row) * K + kb + kc * 8;
            cp_async16(d,         Bh + boff, true);
            cp_async16(d + BMATB, Bl + boff, true);
        }
        CP_COMMIT();
    };

    issue(0);
    if (KT > 1) issue(1);

    const int arow = wm + (lane & 15);
    const int acO  = (lane >> 4) << 3;
    const int brow = wn + (lane & 7) + ((lane >> 4) << 3);
    const int bcO  = ((lane >> 3) & 1) << 3;

    for (int kt = 0; kt < KT; kt++) {
        CP_WAIT1();
        __syncthreads();
        if (kt + 2 < KT) issue(kt + 2);

        const uint32_t base = sb + (kt % 3) * D::STG;
#pragma unroll
        for (int ks = 0; ks < 2; ks++) {
            const int k0 = ks * 16;
            uint32_t aH[D::MT][4], aL[D::MT][4], bH[2][4], bL[2][4];
#pragma unroll
            for (int mt = 0; mt < D::MT; mt++) {
                const int r = arow + mt * 16;
                uint32_t ad = base + swz(r, (k0 + acO) >> 3);
                ldsm_x4(aH[mt], ad);
                ldsm_x4(aL[mt], ad + D::AMATB);
            }
#pragma unroll
            for (int n2 = 0; n2 < 2; n2++) {
                const int r = brow + n2 * 16;
                uint32_t bd = base + 2 * D::AMATB + swz(r, (k0 + bcO) >> 3);
                ldsm_x4(bH[n2], bd);
                ldsm_x4(bL[n2], bd + BMATB);
            }
#pragma unroll
            for (int mt = 0; mt < D::MT; mt++)
#pragma unroll
                for (int nt = 0; nt < 4; nt++) {
                    const int n2 = nt >> 1, hb = (nt & 1) * 2;
                    mma16816(acc[mt][nt], aH[mt], bH[n2][hb], bH[n2][hb + 1]);
                    mma16816(acc[mt][nt], aH[mt], bL[n2][hb], bL[n2][hb + 1]);
                    mma16816(acc[mt][nt], aL[mt], bH[n2][hb], bH[n2][hb + 1]);
                }
        }
    }

#pragma unroll
    for (int mt = 0; mt < D::MT; mt++) {
        const int r0 = bm * BM + wm + mt * 16 + (lane >> 2);
#pragma unroll
        for (int nt = 0; nt < 4; nt++) {
            const int col = bn * 128 + wn + nt * 8 + (lane & 3) * 2;
            float* c = acc[mt][nt];
            float bx = 0.f, by = 0.f;
            if (BIAS) { float2 bv = *(const float2*)(bias + col); bx = bv.x; by = bv.y; }
#pragma unroll
            for (int hh = 0; hh < 2; hh++) {
                const int r = r0 + hh * 8;
                if (r >= Mr) continue;
                float v0 = c[hh * 2 + 0], v1 = c[hh * 2 + 1];
                if (BIAS) { v0 += bx; v1 += by; }
                if (GELU) { v0 = gelu_tanh(v0); v1 = gelu_tanh(v1); }
                if (OUTHL) {
                    uint32_t hi, lo;
                    split2(v0, v1, hi, lo);
                    *(uint32_t*)(Oh + (size_t)r * N + col) = hi;
                    *(uint32_t*)(Ol + (size_t)r * N + col) = lo;
                } else {
                    if (RES) {
                        float2 rv = *(const float2*)(resid + (size_t)r * N + col);
                        v0 += rv.x; v1 += rv.y;
                    }
                    *(float2*)(C + (size_t)r * N + col) = make_float2(v0, v1);
                }
            }
        }
    }
}

// =================== tensor-core flash attention (R10 config + Q in regs) ===
// 128 threads (4 warps), 64 queries per block; 2-stage KV pipeline.
#define APITCH 72
#define AMATB_A 9216
#define ATTN_SMEM (10 * AMATB_A)

__global__ __launch_bounds__(128)
void attn_tc(const __nv_bfloat16* __restrict__ QKVh,
             const __nv_bfloat16* __restrict__ QKVl,
             __nv_bfloat16* __restrict__ Oh, __nv_bfloat16* __restrict__ Ol)
{
    extern __shared__ char asmem[];
    const uint32_t sb = smem_u32(asmem);
    const uint32_t oQh = 0, oQl = AMATB_A;
    const int qb = gridDim.x - 1 - blockIdx.x;    // heavy blocks first
    const int h = blockIdx.y;
    const int tid = threadIdx.x, wid = tid >> 5, lane = tid & 31;
    const int wr = wid * 16;

#pragma unroll
    for (int i = 0; i < 4; i++) {
        int idx = tid + i * 128;
        int row = idx >> 3, ch = idx & 7;
        size_t goff = (size_t)(qb * 64 + row) * QKVN + h * HD + ch * 8;
        uint32_t soff = row * (APITCH * 2) + ch * 16;
        cp_async16(sb + oQh + soff, QKVh + goff, true);
        cp_async16(sb + oQl + soff, QKVl + goff, true);
    }
    CP_COMMIT();

    auto issueKV = [&](int kb) {
        const uint32_t st = sb + 2 * AMATB_A + (kb & 1) * (4 * AMATB_A);
#pragma unroll
        for (int i = 0; i < 4; i++) {
            int idx = tid + i * 128;
            int row = idx >> 3, ch = idx & 7;
            size_t gK = (size_t)(kb * 64 + row) * QKVN + DIM + h * HD + ch * 8;
            size_t gV = (size_t)(kb * 64 + row) * QKVN + 2 * DIM + h * HD + ch * 8;
            uint32_t soff = row * (APITCH * 2) + ch * 16;
            cp_async16(st + soff,               QKVh + gK, true);
            cp_async16(st + AMATB_A + soff,     QKVl + gK, true);
            cp_async16(st + 2 * AMATB_A + soff, QKVh + gV, true);
            cp_async16(st + 3 * AMATB_A + soff, QKVl + gV, true);
        }
        CP_COMMIT();
    };

    issueKV(0);
    if (qb >= 1) issueKV(1);

    float m_[2] = {-1e30f, -1e30f}, l_[2] = {0.f, 0.f};
    float ov[8][4];
#pragma unroll
    for (int i = 0; i < 8; i++)
#pragma unroll
        for (int j = 0; j < 4; j++) ov[i][j] = 0.f;
    const float scale = 0.125f;

    const int ar = wr + (lane & 15);
    const int ac = (lane >> 4) << 3;
    const int br = (lane & 7) + ((lane >> 4) << 3);
    const int bc = ((lane >> 3) & 1) << 3;
    const int vrb = (lane & 7) + (((lane >> 3) & 1) << 3);
    const int vcb = (lane >> 4) << 3;
    const int lr0 = lane >> 2;
    const int lc0 = (lane & 3) * 2;

    // Q fragments: loaded once after the first KV wait (Q group has completed
    // by then — it was committed before KV group 0).
    uint32_t qH[4][4], qL[4][4];
    bool qloaded = false;

    for (int kb = 0; kb <= qb; kb++) {
        if (kb + 1 <= qb) { CP_WAIT1(); } else { CP_WAIT0(); }
        __syncthreads();

        if (!qloaded) {
            qloaded = true;
#pragma unroll
            for (int ks = 0; ks < 4; ks++) {
                uint32_t ao = sb + (ar * APITCH + ks * 16 + ac) * 2;
                ldsm_x4(qH[ks], ao + oQh);
                ldsm_x4(qL[ks], ao + oQl);
            }
        }

        const uint32_t st  = sb + 2 * AMATB_A + (kb & 1) * (4 * AMATB_A);
        const uint32_t oKh = st, oKl = st + AMATB_A;
        const uint32_t oVh = st + 2 * AMATB_A, oVl = st + 3 * AMATB_A;

        float sv[8][4];
#pragma unroll
        for (int i = 0; i < 8; i++)
#pragma unroll
            for (int j = 0; j < 4; j++) sv[i][j] = 0.f;

#pragma unroll
        for (int ks = 0; ks < 4; ks++) {
#pragma unroll
            for (int g = 0; g < 4; g++) {
                uint32_t bH4[4], bL4[4];
                uint32_t bo = ((g * 16 + br) * APITCH + ks * 16 + bc) * 2;
                ldsm_x4(bH4, bo + oKh);
                ldsm_x4(bL4, bo + oKl);
                mma16816(sv[2 * g],     qH[ks], bH4[0], bH4[1]);
                mma16816(sv[2 * g],     qH[ks], bL4[0], bL4[1]);
                mma16816(sv[2 * g],     qL[ks], bH4[0], bH4[1]);
                mma16816(sv[2 * g + 1], qH[ks], bH4[2], bH4[3]);
                mma16816(sv[2 * g + 1], qH[ks], bL4[2], bL4[3]);
                mma16816(sv[2 * g + 1], qL[ks], bH4[2], bH4[3]);
            }
        }

#pragma unroll
        for (int nt = 0; nt < 8; nt++)
#pragma unroll
            for (int e = 0; e < 4; e++) {
                float x = sv[nt][e] * scale;
                if (kb == qb) {
                    int kcol = nt * 8 + lc0 + (e & 1);
                    int qrow = wr + lr0 + ((e >> 1) << 3);
                    if (kcol > qrow) x = -1e30f;
                }
                sv[nt][e] = x;
            }

        float mx0 = -1e30f, mx1 = -1e30f;
#pragma unroll
        for (int nt = 0; nt < 8; nt++) {
            mx0 = fmaxf(mx0, fmaxf(sv[nt][0], sv[nt][1]));
            mx1 = fmaxf(mx1, fmaxf(sv[nt][2], sv[nt][3]));
        }
        mx0 = fmaxf(mx0, __shfl_xor_sync(0xffffffffu, mx0, 1));
        mx0 = fmaxf(mx0, __shfl_xor_sync(0xffffffffu, mx0, 2));
        mx1 = fmaxf(mx1, __shfl_xor_sync(0xffffffffu, mx1, 1));
        mx1 = fmaxf(mx1, __shfl_xor_sync(0xffffffffu, mx1, 2));
        float mn0 = fmaxf(m_[0], mx0), mn1 = fmaxf(m_[1], mx1);
        float cr0 = __expf(m_[0] - mn0), cr1 = __expf(m_[1] - mn1);
        float sum0 = 0.f, sum1 = 0.f;
#pragma unroll
        for (int nt = 0; nt < 8; nt++) {
            float p0 = __expf(sv[nt][0] - mn0);
            float p1 = __expf(sv[nt][1] - mn0);
            float p2 = __expf(sv[nt][2] - mn1);
            float p3 = __expf(sv[nt][3] - mn1);
            sv[nt][0] = p0; sv[nt][1] = p1; sv[nt][2] = p2; sv[nt][3] = p3;
            sum0 += p0 + p1;
            sum1 += p2 + p3;
        }
        sum0 += __shfl_xor_sync(0xffffffffu, sum0, 1);
        sum0 += __shfl_xor_sync(0xffffffffu, sum0, 2);
        sum1 += __shfl_xor_sync(0xffffffffu, sum1, 1);
        sum1 += __shfl_xor_sync(0xffffffffu, sum1, 2);
        l_[0] = l_[0] * cr0 + sum0;
        l_[1] = l_[1] * cr1 + sum1;
        m_[0] = mn0; m_[1] = mn1;
#pragma unroll
        for (int nt = 0; nt < 8; nt++) {
            ov[nt][0] *= cr0; ov[nt][1] *= cr0;
            ov[nt][2] *= cr1; ov[nt][3] *= cr1;
        }

#pragma unroll
        for (int s = 0; s < 4; s++) {
            uint32_t pH[4], pL[4];
            split2(sv[2 * s][0],     sv[2 * s][1],     pH[0], pL[0]);
            split2(sv[2 * s][2],     sv[2 * s][3],     pH[1], pL[1]);
            split2(sv[2 * s + 1][0], sv[2 * s + 1][1], pH[2], pL[2]);
            split2(sv[2 * s + 1][2], sv[2 * s + 1][3], pH[3], pL[3]);
            const int vrow = s * 16 + vrb;
#pragma unroll
            for (int g = 0; g < 4; g++) {
                uint32_t vH4[4], vL4[4];
                uint32_t vo = (vrow * APITCH + g * 16 + vcb) * 2;
                ldsm_x4t(vH4, vo + oVh);
                ldsm_x4t(vL4, vo + oVl);
                mma16816(ov[2 * g],     pH, vH4[0], vH4[1]);
                mma16816(ov[2 * g],     pH, vL4[0], vL4[1]);
                mma16816(ov[2 * g],     pL, vH4[0], vH4[1]);
                mma16816(ov[2 * g + 1], pH, vH4[2], vH4[3]);
                mma16816(ov[2 * g + 1], pH, vL4[2], vL4[3]);
                mma16816(ov[2 * g + 1], pL, vH4[2], vH4[3]);
            }
        }

        __syncthreads();
        if (kb + 2 <= qb) issueKV(kb + 2);
    }

    const float inv0 = 1.0f / l_[0], inv1 = 1.0f / l_[1];
    const int gr0 = qb * 64 + wr + (lane >> 2);
    const int cb  = h * HD + (lane & 3) * 2;
#pragma unroll
    for (int nt = 0; nt < 8; nt++) {
        const int col = cb + nt * 8;
        uint32_t hi, lo;
        split2(ov[nt][0] * inv0, ov[nt][1] * inv0, hi, lo);
        *(uint32_t*)(Oh + (size_t)gr0 * DIM + col) = hi;
        *(uint32_t*)(Ol + (size_t)gr0 * DIM + col) = lo;
        split2(ov[nt][2] * inv1, ov[nt][3] * inv1, hi, lo);
        *(uint32_t*)(Oh + (size_t)(gr0 + 8) * DIM + col) = hi;
        *(uint32_t*)(Ol + (size_t)(gr0 + 8) * DIM + col) = lo;
    }
}

// ---------------- launch ----------------------------------------------------
extern "C" void kernel_launch(void* const* d_in, const int* in_sizes, int n_in,
                              void* d_out, int out_size)
{
    const int*   tokens = (const int*)  d_in[0];
    const float* emb    = (const float*)d_in[1];
    const float* pos    = (const float*)d_in[2];
    const float* mem    = (const float*)d_in[3];
    const float* ln1_s  = (const float*)d_in[4];
    const float* ln1_b  = (const float*)d_in[5];
    const float* wq     = (const float*)d_in[6];
    const float* wk     = (const float*)d_in[7];
    const float* wv     = (const float*)d_in[8];
    const float* wo     = (const float*)d_in[9];
    const float* ln2_s  = (const float*)d_in[10];
    const float* ln2_b  = (const float*)d_in[11];
    const float* w1     = (const float*)d_in[12];
    const float* b1     = (const float*)d_in[13];
    const float* w2     = (const float*)d_in[14];
    const float* b2     = (const float*)d_in[15];
    const float* lnm_s  = (const float*)d_in[16];
    const float* lnm_b  = (const float*)d_in[17];

    float *X;
    __nv_bfloat16 *Nh, *Nl, *QKVh, *QKVl, *Aoh, *Aol, *Fh, *Fl, *Wh, *Wl;
    cudaGetSymbolAddress((void**)&X,    g_X);
    cudaGetSymbolAddress((void**)&Nh,   g_Nh);
    cudaGetSymbolAddress((void**)&Nl,   g_Nl);
    cudaGetSymbolAddress((void**)&QKVh, g_QKVh);
    cudaGetSymbolAddress((void**)&QKVl, g_QKVl);
    cudaGetSymbolAddress((void**)&Aoh,  g_Ahp);
    cudaGetSymbolAddress((void**)&Aol,  g_Alp);
    cudaGetSymbolAddress((void**)&Fh,   g_Fh);
    cudaGetSymbolAddress((void**)&Fl,   g_Fl);
    cudaGetSymbolAddress((void**)&Wh,   g_Wh);
    cudaGetSymbolAddress((void**)&Wl,   g_Wl);

    const int SMEM128 = GemmDims<128>::SMEM;   // 98304
    const int SMEM64  = GemmDims<64>::SMEM;    // 73728

    cudaFuncSetAttribute(attn_tc, cudaFuncAttributeMaxDynamicSharedMemorySize, ATTN_SMEM);
    cudaFuncSetAttribute(gemm_tc<128, false, false, false, true >, cudaFuncAttributeMaxDynamicSharedMemorySize, SMEM128);
    cudaFuncSetAttribute(gemm_tc<128, true,  false, true,  true >, cudaFuncAttributeMaxDynamicSharedMemorySize, SMEM128);
    cudaFuncSetAttribute(gemm_tc<64,  false, true,  false, false>, cudaFuncAttributeMaxDynamicSharedMemorySize, SMEM64);
    cudaFuncSetAttribute(gemm_tc<64,  false, true,  true,  false>, cudaFuncAttributeMaxDynamicSharedMemorySize, SMEM64);

    conv_all<<<(N4_TOT + 255) / 256, 256>>>(wq, wk, wv, wo, w1, w2, Wh, Wl);
    embed_kernel<<<(S_TOT * DIM + 255) / 256, 256>>>(tokens, emb, pos, mem, X);

    const dim3 gQKV(QKVN / 128, (S_TOT + 127) / 128);   // (18, 17)
    const dim3 gFF1 (HID / 128, (S_TOT + 127) / 128);   // (24, 17)
    const dim3 gP64 (DIM / 128, S_TOT / 64);            // (6, 33)

    for (int l = 0; l < NLAYER; l++) {
        ln_hl_kernel<<<S_TOT, 384>>>(X, ln1_s + l * DIM, ln1_b + l * DIM, Nh, Nl);

        gemm_tc<128, false, false, false, true><<<gQKV, 256, SMEM128>>>(
            Nh, Nl,
            Wh + OFF_QKV + (size_t)l * 3 * DIM * DIM, Wl + OFF_QKV + (size_t)l * 3 * DIM * DIM,
            nullptr, nullptr, nullptr, QKVh, QKVl, S_TOT, QKVN, DIM);

        attn_tc<<<dim3(S_TOT / 64, NHEAD), 128, ATTN_SMEM>>>(QKVh, QKVl, Aoh, Aol);

        gemm_tc<64, false, true, false, false><<<gP64, 256, SMEM64>>>(
            Aoh, Aol, Wh + OFF_WO + (size_t)l * DIM * DIM, Wl + OFF_WO + (size_t)l * DIM * DIM,
            nullptr, X, X, nullptr, nullptr, S_TOT, DIM, DIM);

        ln_hl_kernel<<<S_TOT, 384>>>(X, ln2_s + l * DIM, ln2_b + l * DIM, Nh, Nl);

        gemm_tc<128, true, false, true, true><<<gFF1, 256, SMEM128>>>(
            Nh, Nl, Wh + OFF_W1 + (size_t)l * HID * DIM, Wl + OFF_W1 + (size_t)l * HID * DIM,
            b1 + l * HID, nullptr, nullptr, Fh, Fl, S_TOT, HID, DIM);

        gemm_tc<64, false, true, true, false><<<gP64, 256, SMEM64>>>(
            Fh, Fl, Wh + OFF_W2 + (size_t)l * DIM * HID, Wl + OFF_W2 + (size_t)l * DIM * HID,
            b2 + l * DIM, X, X, nullptr, nullptr, S_TOT, DIM, HID);
    }

    ln_kernel<<<MEMN, 384>>>(X, lnm_s, lnm_b, (float*)d_out, S_TOT - MEMN);
}

// round 15
// speedup vs baseline: 1.0289x; 1.0121x over previous
#include <cuda_runtime.h>
#include <cuda_bf16.h>
#include <cstdint>

#define S_TOT 2112          // 64 mem + 2048 tokens
#define MEMN  64
#define DIM   768
#define HID   3072
#define NHEAD 12
#define HD    64
#define NLAYER 4
#define QKVN  (3 * DIM)     // 2304

// ---------------- scratch (device globals; no allocation allowed) ----------
__device__ __align__(16) float g_X [S_TOT * DIM];

__device__ __align__(16) __nv_bfloat16 g_Nh[S_TOT * DIM];
__device__ __align__(16) __nv_bfloat16 g_Nl[S_TOT * DIM];
__device__ __align__(16) __nv_bfloat16 g_QKVh[S_TOT * QKVN];
__device__ __align__(16) __nv_bfloat16 g_QKVl[S_TOT * QKVN];
__device__ __align__(16) __nv_bfloat16 g_Ahp[S_TOT * DIM];
__device__ __align__(16) __nv_bfloat16 g_Alp[S_TOT * DIM];
__device__ __align__(16) __nv_bfloat16 g_Fh[S_TOT * HID];
__device__ __align__(16) __nv_bfloat16 g_Fl[S_TOT * HID];

// preconverted weights (hi/lo bf16), all layers
#define WSZ_P   (NLAYER * DIM * DIM)
#define WSZ_FF  (NLAYER * HID * DIM)
#define OFF_QKV 0
#define OFF_WO  (OFF_QKV + 3 * WSZ_P)
#define OFF_W1  (OFF_WO + WSZ_P)
#define OFF_W2  (OFF_W1 + WSZ_FF)
#define WTOT    (OFF_W2 + WSZ_FF)
__device__ __align__(16) __nv_bfloat16 g_Wh[WTOT];
__device__ __align__(16) __nv_bfloat16 g_Wl[WTOT];

// =================== helpers ================================================
__device__ __forceinline__ uint32_t smem_u32(const void* p) {
    uint32_t a;
    asm("{ .reg .u64 t; cvta.to.shared.u64 t, %1; cvt.u32.u64 %0, t; }"
        : "=r"(a) : "l"(p));
    return a;
}
__device__ __forceinline__ void ldsm_x4(uint32_t* r, uint32_t addr) {
    asm volatile("ldmatrix.sync.aligned.m8n8.x4.shared.b16 {%0,%1,%2,%3}, [%4];"
                 : "=r"(r[0]), "=r"(r[1]), "=r"(r[2]), "=r"(r[3]) : "r"(addr));
}
__device__ __forceinline__ void ldsm_x4t(uint32_t* r, uint32_t addr) {
    asm volatile("ldmatrix.sync.aligned.m8n8.x4.trans.shared.b16 {%0,%1,%2,%3}, [%4];"
                 : "=r"(r[0]), "=r"(r[1]), "=r"(r[2]), "=r"(r[3]) : "r"(addr));
}
__device__ __forceinline__ void mma16816(float* c, const uint32_t* a,
                                         const uint32_t b0, const uint32_t b1) {
    asm volatile("mma.sync.aligned.m16n8k16.row.col.f32.bf16.bf16.f32 "
                 "{%0,%1,%2,%3}, {%4,%5,%6,%7}, {%8,%9}, {%0,%1,%2,%3};"
                 : "+f"(c[0]), "+f"(c[1]), "+f"(c[2]), "+f"(c[3])
                 : "r"(a[0]), "r"(a[1]), "r"(a[2]), "r"(a[3]), "r"(b0), "r"(b1));
}
__device__ __forceinline__ void cp_async16(uint32_t dst, const void* src, bool pred) {
    int sz = pred ? 16 : 0;
    asm volatile("cp.async.cg.shared.global [%0], [%1], 16, %2;"
                 :: "r"(dst), "l"(src), "r"(sz) : "memory");
}
#define CP_COMMIT() asm volatile("cp.async.commit_group;" ::: "memory")
#define CP_WAIT1()  asm volatile("cp.async.wait_group 1;" ::: "memory")
#define CP_WAIT0()  asm volatile("cp.async.wait_group 0;" ::: "memory")

// XOR chunk swizzle: 64B rows, 4 chunks of 16B; conflict-free for ldmatrix.
__device__ __forceinline__ uint32_t swz(int row, int chunk) {
    return (uint32_t)(row * 64 + ((chunk ^ ((row >> 1) & 3)) << 4));
}

__device__ __forceinline__ void split4(float4 v, uint2& hi, uint2& lo)
{
    __nv_bfloat16 h0 = __float2bfloat16(v.x);
    __nv_bfloat16 h1 = __float2bfloat16(v.y);
    __nv_bfloat16 h2 = __float2bfloat16(v.z);
    __nv_bfloat16 h3 = __float2bfloat16(v.w);
    __nv_bfloat16 l0 = __float2bfloat16(v.x - __bfloat162float(h0));
    __nv_bfloat16 l1 = __float2bfloat16(v.y - __bfloat162float(h1));
    __nv_bfloat16 l2 = __float2bfloat16(v.z - __bfloat162float(h2));
    __nv_bfloat16 l3 = __float2bfloat16(v.w - __bfloat162float(h3));
    hi.x = (uint32_t)__bfloat16_as_ushort(h1) << 16 | __bfloat16_as_ushort(h0);
    hi.y = (uint32_t)__bfloat16_as_ushort(h3) << 16 | __bfloat16_as_ushort(h2);
    lo.x = (uint32_t)__bfloat16_as_ushort(l1) << 16 | __bfloat16_as_ushort(l0);
    lo.y = (uint32_t)__bfloat16_as_ushort(l3) << 16 | __bfloat16_as_ushort(l2);
}
__device__ __forceinline__ void split2(float a, float b, uint32_t& hi, uint32_t& lo)
{
    __nv_bfloat16 ha = __float2bfloat16(a), hb = __float2bfloat16(b);
    __nv_bfloat16 la = __float2bfloat16(a - __bfloat162float(ha));
    __nv_bfloat16 lb = __float2bfloat16(b - __bfloat162float(hb));
    hi = (uint32_t)__bfloat16_as_ushort(hb) << 16 | __bfloat16_as_ushort(ha);
    lo = (uint32_t)__bfloat16_as_ushort(lb) << 16 | __bfloat16_as_ushort(la);
}

// ---------------- unified weight pre-conversion (1 launch) ------------------
#define N4_QKV (3 * WSZ_P / 4)
#define N4_WO  (WSZ_P / 4)
#define N4_FF  (WSZ_FF / 4)
#define N4_TOT (N4_QKV + N4_WO + 2 * N4_FF)

__global__ void conv_all(const float* __restrict__ wq, const float* __restrict__ wk,
                         const float* __restrict__ wv, const float* __restrict__ wo,
                         const float* __restrict__ w1, const float* __restrict__ w2,
                         __nv_bfloat16* __restrict__ Wh, __nv_bfloat16* __restrict__ Wl)
{
    int i = blockIdx.x * 256 + threadIdx.x;
    if (i >= N4_TOT) return;
    const float* src;
    size_t se, de;
    if (i < N4_QKV) {
        const int n4l = DIM * DIM / 4;
        const int per_t = NLAYER * n4l;
        int t = i / per_t;
        int r = i - t * per_t;
        int l = r / n4l, e = r - l * n4l;
        src = (t == 0) ? wq : (t == 1) ? wk : wv;
        se = (size_t)l * n4l + e;
        de = (size_t)(OFF_QKV / 4) + (size_t)l * (3 * n4l) + (size_t)t * n4l + e;
    } else if (i < N4_QKV + N4_WO) {
        int e = i - N4_QKV;
        src = wo; se = e; de = OFF_WO / 4 + e;
    } else if (i < N4_QKV + N4_WO + N4_FF) {
        int e = i - N4_QKV - N4_WO;
        src = w1; se = e; de = OFF_W1 / 4 + e;
    } else {
        int e = i - N4_QKV - N4_WO - N4_FF;
        src = w2; se = e; de = OFF_W2 / 4 + e;
    }
    float4 v = ((const float4*)src)[se];
    uint2 hi, lo;
    split4(v, hi, lo);
    ((uint2*)Wh)[de] = hi;
    ((uint2*)Wl)[de] = lo;
}

// ---------------- embedding ------------------------------------------------
__global__ void embed_kernel(const int* __restrict__ tokens,
                             const float* __restrict__ emb,
                             const float* __restrict__ pos,
                             const float* __restrict__ mem,
                             float* __restrict__ X)
{
    int idx = blockIdx.x * 256 + threadIdx.x;
    if (idx >= S_TOT * DIM) return;
    int s = idx / DIM;
    int d = idx - s * DIM;
    if (s < MEMN) {
        X[idx] = mem[s * DIM + d];
    } else {
        int t = s - MEMN;
        X[idx] = emb[tokens[t] * DIM + d] + pos[t * DIM + d];
    }
}

// ---------------- layernorm (384 threads, float2 per thread) ----------------
__device__ __forceinline__ void ln_stats384(float a, float b, float& mean, float& inv)
{
    int t = threadIdx.x;
    float s = a + b;
    float q = a * a + b * b;
#pragma unroll
    for (int off = 16; off; off >>= 1) {
        s += __shfl_xor_sync(0xffffffffu, s, off);
        q += __shfl_xor_sync(0xffffffffu, q, off);
    }
    __shared__ float rs[12], rq[12];
    __shared__ float mean_sh, inv_sh;
    int w = t >> 5;
    if ((t & 31) == 0) { rs[w] = s; rq[w] = q; }
    __syncthreads();
    if (t == 0) {
        float S = 0.f, Q = 0.f;
#pragma unroll
        for (int i = 0; i < 12; i++) { S += rs[i]; Q += rq[i]; }
        float mn = S * (1.0f / DIM);
        float var = Q * (1.0f / DIM) - mn * mn;
        mean_sh = mn;
        inv_sh  = rsqrtf(var + 1e-5f);
    }
    __syncthreads();
    mean = mean_sh;
    inv  = inv_sh;
}

__global__ void ln_hl_kernel(const float* __restrict__ X,
                             const float* __restrict__ g,
                             const float* __restrict__ bt,
                             __nv_bfloat16* __restrict__ oh,
                             __nv_bfloat16* __restrict__ ol)
{
    int row = blockIdx.x;
    int t = threadIdx.x;
    float2 v = ((const float2*)(X + (size_t)row * DIM))[t];
    float mean, inv;
    ln_stats384(v.x, v.y, mean, inv);
    float2 gv = ((const float2*)g)[t];
    float2 bv = ((const float2*)bt)[t];
    float y0 = (v.x - mean) * inv * gv.x + bv.x;
    float y1 = (v.y - mean) * inv * gv.y + bv.y;
    uint32_t hi, lo;
    split2(y0, y1, hi, lo);
    ((uint32_t*)oh)[(size_t)row * (DIM / 2) + t] = hi;
    ((uint32_t*)ol)[(size_t)row * (DIM / 2) + t] = lo;
}

__global__ void ln_kernel(const float* __restrict__ X,
                          const float* __restrict__ g,
                          const float* __restrict__ bt,
                          float* __restrict__ out, int in_off)
{
    int row = blockIdx.x + in_off;
    int t = threadIdx.x;
    float2 v = ((const float2*)(X + (size_t)row * DIM))[t];
    float mean, inv;
    ln_stats384(v.x, v.y, mean, inv);
    float2 gv = ((const float2*)g)[t];
    float2 bv = ((const float2*)bt)[t];
    float y0 = (v.x - mean) * inv * gv.x + bv.x;
    float y1 = (v.y - mean) * inv * gv.y + bv.y;
    ((float2*)(out + (size_t)blockIdx.x * DIM))[t] = make_float2(y0, y1);
}

__device__ __forceinline__ float gelu_tanh(float x)
{
    const float c = 0.7978845608028654f;
    float u = c * (x + 0.044715f * x * x * x);
    return 0.5f * x * (1.0f + tanhf(u));
}

// =================== bf16x3 GEMM, CTA BMx128, 3-stage swizzled, 2 CTAs/SM ===
// Term-major MMA ordering: each accumulator's 3 terms separated by 4*MT
// independent MMAs (RAW chain broken).
#define BMATB  8192                  // B: 128 rows x 64B

template <int BM>
struct GemmDims {
    static const int AMATB = BM * 64;                 // A: BM rows x 64B
    static const int STG   = 2 * AMATB + 2 * BMATB;
    static const int SMEM  = 3 * STG;                 // 3 stages
    static const int MT    = BM / 32;
};

template <int BM, bool GELU, bool RES, bool BIAS, bool OUTHL>
__global__ __launch_bounds__(256, 2)
void gemm_tc(const __nv_bfloat16* __restrict__ Ah, const __nv_bfloat16* __restrict__ Al,
             const __nv_bfloat16* __restrict__ Bh, const __nv_bfloat16* __restrict__ Bl,
             const float* __restrict__ bias, const float* __restrict__ resid,
             float* __restrict__ C,
             __nv_bfloat16* __restrict__ Oh, __nv_bfloat16* __restrict__ Ol,
             int Mr, int N, int K)
{
    typedef GemmDims<BM> D;
    extern __shared__ char smem[];
    const uint32_t sb = smem_u32(smem);
    const int tid = threadIdx.x, wid = tid >> 5, lane = tid & 31;
    const int bm = blockIdx.y, bn = blockIdx.x;
    const int wm = (wid >> 2) * (BM / 2);
    const int wn = (wid & 3) * 32;
    const int KT = K >> 5;

    float acc[D::MT][4][4];
#pragma unroll
    for (int i = 0; i < D::MT; i++)
#pragma unroll
        for (int j = 0; j < 4; j++)
#pragma unroll
            for (int k = 0; k < 4; k++) acc[i][j][k] = 0.f;

    auto issue = [&](int kt) {
        const uint32_t stg = sb + (kt % 3) * D::STG;
        const int kb = kt * 32;
#pragma unroll
        for (int i = 0; i < BM / 64; i++) {
            int e = tid + i * 256;
            int row = e >> 2, kc = e & 3;
            uint32_t d = stg + swz(row, kc);
            int ga = bm * BM + row;
            const bool av = ga < Mr;
            if (!av) ga = 0;
            const size_t aoff = (size_t)ga * K + kb + kc * 8;
            cp_async16(d,            Ah + aoff, av);
            cp_async16(d + D::AMATB, Al + aoff, av);
        }
#pragma unroll
        for (int i = 0; i < 2; i++) {
            int e = tid + i * 256;
            int row = e >> 2, kc = e & 3;
            uint32_t d = stg + 2 * D::AMATB + swz(row, kc);
            const size_t boff = (size_t)(bn * 128 + row) * K + kb + kc * 8;
            cp_async16(d,         Bh + boff, true);
            cp_async16(d + BMATB, Bl + boff, true);
        }
        CP_COMMIT();
    };

    issue(0);
    if (KT > 1) issue(1);

    const int arow = wm + (lane & 15);
    const int acO  = (lane >> 4) << 3;
    const int brow = wn + (lane & 7) + ((lane >> 4) << 3);
    const int bcO  = ((lane >> 3) & 1) << 3;

    for (int kt = 0; kt < KT; kt++) {
        CP_WAIT1();
        __syncthreads();
        if (kt + 2 < KT) issue(kt + 2);

        const uint32_t base = sb + (kt % 3) * D::STG;
#pragma unroll
        for (int ks = 0; ks < 2; ks++) {
            const int k0 = ks * 16;
            uint32_t aH[D::MT][4], aL[D::MT][4], bH[2][4], bL[2][4];
#pragma unroll
            for (int mt = 0; mt < D::MT; mt++) {
                const int r = arow + mt * 16;
                uint32_t ad = base + swz(r, (k0 + acO) >> 3);
                ldsm_x4(aH[mt], ad);
                ldsm_x4(aL[mt], ad + D::AMATB);
            }
#pragma unroll
            for (int n2 = 0; n2 < 2; n2++) {
                const int r = brow + n2 * 16;
                uint32_t bd = base + 2 * D::AMATB + swz(r, (k0 + bcO) >> 3);
                ldsm_x4(bH[n2], bd);
                ldsm_x4(bL[n2], bd + BMATB);
            }
            // term-major: break accumulator RAW chains
#pragma unroll
            for (int mt = 0; mt < D::MT; mt++)
#pragma unroll
                for (int nt = 0; nt < 4; nt++) {
                    const int n2 = nt >> 1, hb = (nt & 1) * 2;
                    mma16816(acc[mt][nt], aH[mt], bH[n2][hb], bH[n2][hb + 1]);
                }
#pragma unroll
            for (int mt = 0; mt < D::MT; mt++)
#pragma unroll
                for (int nt = 0; nt < 4; nt++) {
                    const int n2 = nt >> 1, hb = (nt & 1) * 2;
                    mma16816(acc[mt][nt], aH[mt], bL[n2][hb], bL[n2][hb + 1]);
                }
#pragma unroll
            for (int mt = 0; mt < D::MT; mt++)
#pragma unroll
                for (int nt = 0; nt < 4; nt++) {
                    const int n2 = nt >> 1, hb = (nt & 1) * 2;
                    mma16816(acc[mt][nt], aL[mt], bH[n2][hb], bH[n2][hb + 1]);
                }
        }
    }

#pragma unroll
    for (int mt = 0; mt < D::MT; mt++) {
        const int r0 = bm * BM + wm + mt * 16 + (lane >> 2);
#pragma unroll
        for (int nt = 0; nt < 4; nt++) {
            const int col = bn * 128 + wn + nt * 8 + (lane & 3) * 2;
            float* c = acc[mt][nt];
            float bx = 0.f, by = 0.f;
            if (BIAS) { float2 bv = *(const float2*)(bias + col); bx = bv.x; by = bv.y; }
#pragma unroll
            for (int hh = 0; hh < 2; hh++) {
                const int r = r0 + hh * 8;
                if (r >= Mr) continue;
                float v0 = c[hh * 2 + 0], v1 = c[hh * 2 + 1];
                if (BIAS) { v0 += bx; v1 += by; }
                if (GELU) { v0 = gelu_tanh(v0); v1 = gelu_tanh(v1); }
                if (OUTHL) {
                    uint32_t hi, lo;
                    split2(v0, v1, hi, lo);
                    *(uint32_t*)(Oh + (size_t)r * N + col) = hi;
                    *(uint32_t*)(Ol + (size_t)r * N + col) = lo;
                } else {
                    if (RES) {
                        float2 rv = *(const float2*)(resid + (size_t)r * N + col);
                        v0 += rv.x; v1 += rv.y;
                    }
                    *(float2*)(C + (size_t)r * N + col) = make_float2(v0, v1);
                }
            }
        }
    }
}

// =================== tensor-core flash attention (R10 + interleaved MMA) ====
#define APITCH 72
#define AMATB_A 9216
#define ATTN_SMEM (10 * AMATB_A)

__global__ __launch_bounds__(128)
void attn_tc(const __nv_bfloat16* __restrict__ QKVh,
             const __nv_bfloat16* __restrict__ QKVl,
             __nv_bfloat16* __restrict__ Oh, __nv_bfloat16* __restrict__ Ol)
{
    extern __shared__ char asmem[];
    const uint32_t sb = smem_u32(asmem);
    const uint32_t oQh = 0, oQl = AMATB_A;
    const int qb = gridDim.x - 1 - blockIdx.x;    // heavy blocks first
    const int h = blockIdx.y;
    const int tid = threadIdx.x, wid = tid >> 5, lane = tid & 31;
    const int wr = wid * 16;

#pragma unroll
    for (int i = 0; i < 4; i++) {
        int idx = tid + i * 128;
        int row = idx >> 3, ch = idx & 7;
        size_t goff = (size_t)(qb * 64 + row) * QKVN + h * HD + ch * 8;
        uint32_t soff = row * (APITCH * 2) + ch * 16;
        cp_async16(sb + oQh + soff, QKVh + goff, true);
        cp_async16(sb + oQl + soff, QKVl + goff, true);
    }
    CP_COMMIT();

    auto issueKV = [&](int kb) {
        const uint32_t st = sb + 2 * AMATB_A + (kb & 1) * (4 * AMATB_A);
#pragma unroll
        for (int i = 0; i < 4; i++) {
            int idx = tid + i * 128;
            int row = idx >> 3, ch = idx & 7;
            size_t gK = (size_t)(kb * 64 + row) * QKVN + DIM + h * HD + ch * 8;
            size_t gV = (size_t)(kb * 64 + row) * QKVN + 2 * DIM + h * HD + ch * 8;
            uint32_t soff = row * (APITCH * 2) + ch * 16;
            cp_async16(st + soff,               QKVh + gK, true);
            cp_async16(st + AMATB_A + soff,     QKVl + gK, true);
            cp_async16(st + 2 * AMATB_A + soff, QKVh + gV, true);
            cp_async16(st + 3 * AMATB_A + soff, QKVl + gV, true);
        }
        CP_COMMIT();
    };

    issueKV(0);
    if (qb >= 1) issueKV(1);

    float m_[2] = {-1e30f, -1e30f}, l_[2] = {0.f, 0.f};
    float ov[8][4];
#pragma unroll
    for (int i = 0; i < 8; i++)
#pragma unroll
        for (int j = 0; j < 4; j++) ov[i][j] = 0.f;
    const float scale = 0.125f;

    const int ar = wr + (lane & 15);
    const int ac = (lane >> 4) << 3;
    const int br = (lane & 7) + ((lane >> 4) << 3);
    const int bc = ((lane >> 3) & 1) << 3;
    const int vrb = (lane & 7) + (((lane >> 3) & 1) << 3);
    const int vcb = (lane >> 4) << 3;
    const int lr0 = lane >> 2;
    const int lc0 = (lane & 3) * 2;

    for (int kb = 0; kb <= qb; kb++) {
        if (kb + 1 <= qb) { CP_WAIT1(); } else { CP_WAIT0(); }
        __syncthreads();

        const uint32_t st  = sb + 2 * AMATB_A + (kb & 1) * (4 * AMATB_A);
        const uint32_t oKh = st, oKl = st + AMATB_A;
        const uint32_t oVh = st + 2 * AMATB_A, oVl = st + 3 * AMATB_A;

        float sv[8][4];
#pragma unroll
        for (int i = 0; i < 8; i++)
#pragma unroll
            for (int j = 0; j < 4; j++) sv[i][j] = 0.f;

#pragma unroll
        for (int ks = 0; ks < 4; ks++) {
            uint32_t aH[4], aL[4];
            uint32_t ao = sb + (ar * APITCH + ks * 16 + ac) * 2;
            ldsm_x4(aH, ao + oQh);
            ldsm_x4(aL, ao + oQl);
#pragma unroll
            for (int g = 0; g < 4; g++) {
                uint32_t bH4[4], bL4[4];
                uint32_t bo = ((g * 16 + br) * APITCH + ks * 16 + bc) * 2;
                ldsm_x4(bH4, bo + oKh);
                ldsm_x4(bL4, bo + oKl);
                // interleave the two accumulators to break RAW chains
                mma16816(sv[2 * g],     aH, bH4[0], bH4[1]);
                mma16816(sv[2 * g + 1], aH, bH4[2], bH4[3]);
                mma16816(sv[2 * g],     aH, bL4[0], bL4[1]);
                mma16816(sv[2 * g + 1], aH, bL4[2], bL4[3]);
                mma16816(sv[2 * g],     aL, bH4[0], bH4[1]);
                mma16816(sv[2 * g + 1], aL, bH4[2], bH4[3]);
            }
        }

#pragma unroll
        for (int nt = 0; nt < 8; nt++)
#pragma unroll
            for (int e = 0; e < 4; e++) {
                float x = sv[nt][e] * scale;
                if (kb == qb) {
                    int kcol = nt * 8 + lc0 + (e & 1);
                    int qrow = wr + lr0 + ((e >> 1) << 3);
                    if (kcol > qrow) x = -1e30f;
                }
                sv[nt][e] = x;
            }

        float mx0 = -1e30f, mx1 = -1e30f;
#pragma unroll
        for (int nt = 0; nt < 8; nt++) {
            mx0 = fmaxf(mx0, fmaxf(sv[nt][0], sv[nt][1]));
            mx1 = fmaxf(mx1, fmaxf(sv[nt][2], sv[nt][3]));
        }
        mx0 = fmaxf(mx0, __shfl_xor_sync(0xffffffffu, mx0, 1));
        mx0 = fmaxf(mx0, __shfl_xor_sync(0xffffffffu, mx0, 2));
        mx1 = fmaxf(mx1, __shfl_xor_sync(0xffffffffu, mx1, 1));
        mx1 = fmaxf(mx1, __shfl_xor_sync(0xffffffffu, mx1, 2));
        float mn0 = fmaxf(m_[0], mx0), mn1 = fmaxf(m_[1], mx1);
        float cr0 = __expf(m_[0] - mn0), cr1 = __expf(m_[1] - mn1);
        float sum0 = 0.f, sum1 = 0.f;
#pragma unroll
        for (int nt = 0; nt < 8; nt++) {
            float p0 = __expf(sv[nt][0] - mn0);
            float p1 = __expf(sv[nt][1] - mn0);
            float p2 = __expf(sv[nt][2] - mn1);
            float p3 = __expf(sv[nt][3] - mn1);
            sv[nt][0] = p0; sv[nt][1] = p1; sv[nt][2] = p2; sv[nt][3] = p3;
            sum0 += p0 + p1;
            sum1 += p2 + p3;
        }
        sum0 += __shfl_xor_sync(0xffffffffu, sum0, 1);
        sum0 += __shfl_xor_sync(0xffffffffu, sum0, 2);
        sum1 += __shfl_xor_sync(0xffffffffu, sum1, 1);
        sum1 += __shfl_xor_sync(0xffffffffu, sum1, 2);
        l_[0] = l_[0] * cr0 + sum0;
        l_[1] = l_[1] * cr1 + sum1;
        m_[0] = mn0; m_[1] = mn1;
#pragma unroll
        for (int nt = 0; nt < 8; nt++) {
            ov[nt][0] *= cr0; ov[nt][1] *= cr0;
            ov[nt][2] *= cr1; ov[nt][3] *= cr1;
        }

#pragma unroll
        for (int s = 0; s < 4; s++) {
            uint32_t pH[4], pL[4];
            split2(sv[2 * s][0],     sv[2 * s][1],     pH[0], pL[0]);
            split2(sv[2 * s][2],     sv[2 * s][3],     pH[1], pL[1]);
            split2(sv[2 * s + 1][0], sv[2 * s + 1][1], pH[2], pL[2]);
            split2(sv[2 * s + 1][2], sv[2 * s + 1][3], pH[3], pL[3]);
            const int vrow = s * 16 + vrb;
#pragma unroll
            for (int g = 0; g < 4; g++) {
                uint32_t vH4[4], vL4[4];
                uint32_t vo = (vrow * APITCH + g * 16 + vcb) * 2;
                ldsm_x4t(vH4, vo + oVh);
                ldsm_x4t(vL4, vo + oVl);
                mma16816(ov[2 * g],     pH, vH4[0], vH4[1]);
                mma16816(ov[2 * g + 1], pH, vH4[2], vH4[3]);
                mma16816(ov[2 * g],     pH, vL4[0], vL4[1]);
                mma16816(ov[2 * g + 1], pH, vL4[2], vL4[3]);
                mma16816(ov[2 * g],     pL, vH4[0], vH4[1]);
                mma16816(ov[2 * g + 1], pL, vH4[2], vH4[3]);
            }
        }

        __syncthreads();
        if (kb + 2 <= qb) issueKV(kb + 2);
    }

    const float inv0 = 1.0f / l_[0], inv1 = 1.0f / l_[1];
    const int gr0 = qb * 64 + wr + (lane >> 2);
    const int cb  = h * HD + (lane & 3) * 2;
#pragma unroll
    for (int nt = 0; nt < 8; nt++) {
        const int col = cb + nt * 8;
        uint32_t hi, lo;
        split2(ov[nt][0] * inv0, ov[nt][1] * inv0, hi, lo);
        *(uint32_t*)(Oh + (size_t)gr0 * DIM + col) = hi;
        *(uint32_t*)(Ol + (size_t)gr0 * DIM + col) = lo;
        split2(ov[nt][2] * inv1, ov[nt][3] * inv1, hi, lo);
        *(uint32_t*)(Oh + (size_t)(gr0 + 8) * DIM + col) = hi;
        *(uint32_t*)(Ol + (size_t)(gr0 + 8) * DIM + col) = lo;
    }
}

// ---------------- launch ----------------------------------------------------
extern "C" void kernel_launch(void* const* d_in, const int* in_sizes, int n_in,
                              void* d_out, int out_size)
{
    const int*   tokens = (const int*)  d_in[0];
    const float* emb    = (const float*)d_in[1];
    const float* pos    = (const float*)d_in[2];
    const float* mem    = (const float*)d_in[3];
    const float* ln1_s  = (const float*)d_in[4];
    const float* ln1_b  = (const float*)d_in[5];
    const float* wq     = (const float*)d_in[6];
    const float* wk     = (const float*)d_in[7];
    const float* wv     = (const float*)d_in[8];
    const float* wo     = (const float*)d_in[9];
    const float* ln2_s  = (const float*)d_in[10];
    const float* ln2_b  = (const float*)d_in[11];
    const float* w1     = (const float*)d_in[12];
    const float* b1     = (const float*)d_in[13];
    const float* w2     = (const float*)d_in[14];
    const float* b2     = (const float*)d_in[15];
    const float* lnm_s  = (const float*)d_in[16];
    const float* lnm_b  = (const float*)d_in[17];

    float *X;
    __nv_bfloat16 *Nh, *Nl, *QKVh, *QKVl, *Aoh, *Aol, *Fh, *Fl, *Wh, *Wl;
    cudaGetSymbolAddress((void**)&X,    g_X);
    cudaGetSymbolAddress((void**)&Nh,   g_Nh);
    cudaGetSymbolAddress((void**)&Nl,   g_Nl);
    cudaGetSymbolAddress((void**)&QKVh, g_QKVh);
    cudaGetSymbolAddress((void**)&QKVl, g_QKVl);
    cudaGetSymbolAddress((void**)&Aoh,  g_Ahp);
    cudaGetSymbolAddress((void**)&Aol,  g_Alp);
    cudaGetSymbolAddress((void**)&Fh,   g_Fh);
    cudaGetSymbolAddress((void**)&Fl,   g_Fl);
    cudaGetSymbolAddress((void**)&Wh,   g_Wh);
    cudaGetSymbolAddress((void**)&Wl,   g_Wl);

    const int SMEM128 = GemmDims<128>::SMEM;   // 98304
    const int SMEM64  = GemmDims<64>::SMEM;    // 73728

    cudaFuncSetAttribute(attn_tc, cudaFuncAttributeMaxDynamicSharedMemorySize, ATTN_SMEM);
    cudaFuncSetAttribute(gemm_tc<128, false, false, false, true >, cudaFuncAttributeMaxDynamicSharedMemorySize, SMEM128);
    cudaFuncSetAttribute(gemm_tc<128, true,  false, true,  true >, cudaFuncAttributeMaxDynamicSharedMemorySize, SMEM128);
    cudaFuncSetAttribute(gemm_tc<64,  false, true,  false, false>, cudaFuncAttributeMaxDynamicSharedMemorySize, SMEM64);
    cudaFuncSetAttribute(gemm_tc<64,  false, true,  true,  false>, cudaFuncAttributeMaxDynamicSharedMemorySize, SMEM64);

    conv_all<<<(N4_TOT + 255) / 256, 256>>>(wq, wk, wv, wo, w1, w2, Wh, Wl);
    embed_kernel<<<(S_TOT * DIM + 255) / 256, 256>>>(tokens, emb, pos, mem, X);

    const dim3 gQKV(QKVN / 128, (S_TOT + 127) / 128);   // (18, 17)
    const dim3 gFF1 (HID / 128, (S_TOT + 127) / 128);   // (24, 17)
    const dim3 gP64 (DIM / 128, S_TOT / 64);            // (6, 33)

    for (int l = 0; l < NLAYER; l++) {
        ln_hl_kernel<<<S_TOT, 384>>>(X, ln1_s + l * DIM, ln1_b + l * DIM, Nh, Nl);

        gemm_tc<128, false, false, false, true><<<gQKV, 256, SMEM128>>>(
            Nh, Nl,
            Wh + OFF_QKV + (size_t)l * 3 * DIM * DIM, Wl + OFF_QKV + (size_t)l * 3 * DIM * DIM,
            nullptr, nullptr, nullptr, QKVh, QKVl, S_TOT, QKVN, DIM);

        attn_tc<<<dim3(S_TOT / 64, NHEAD), 128, ATTN_SMEM>>>(QKVh, QKVl, Aoh, Aol);

        gemm_tc<64, false, true, false, false><<<gP64, 256, SMEM64>>>(
            Aoh, Aol, Wh + OFF_WO + (size_t)l * DIM * DIM, Wl + OFF_WO + (size_t)l * DIM * DIM,
            nullptr, X, X, nullptr, nullptr, S_TOT, DIM, DIM);

        ln_hl_kernel<<<S_TOT, 384>>>(X, ln2_s + l * DIM, ln2_b + l * DIM, Nh, Nl);

        gemm_tc<128, true, false, true, true><<<gFF1, 256, SMEM128>>>(
            Nh, Nl, Wh + OFF_W1 + (size_t)l * HID * DIM, Wl + OFF_W1 + (size_t)l * HID * DIM,
            b1 + l * HID, nullptr, nullptr, Fh, Fl, S_TOT, HID, DIM);

        gemm_tc<64, false, true, true, false><<<gP64, 256, SMEM64>>>(
            Fh, Fl, Wh + OFF_W2 + (size_t)l * DIM * HID, Wl + OFF_W2 + (size_t)l * DIM * HID,
            b2 + l * DIM, X, X, nullptr, nullptr, S_TOT, DIM, HID);
    }

    ln_kernel<<<MEMN, 384>>>(X, lnm_s, lnm_b, (float*)d_out, S_TOT - MEMN);
}

// round 16
// speedup vs baseline: 1.0610x; 1.0313x over previous
#include <cuda_runtime.h>
#include <cuda_bf16.h>
#include <cstdint>

#define S_TOT 2112          // 64 mem + 2048 tokens
#define MEMN  64
#define DIM   768
#define HID   3072
#define NHEAD 12
#define HD    64
#define NLAYER 4
#define QKVN  (3 * DIM)     // 2304

// ---------------- scratch (device globals; no allocation allowed) ----------
__device__ __align__(16) float g_X [S_TOT * DIM];

__device__ __align__(16) __nv_bfloat16 g_Nh[S_TOT * DIM];
__device__ __align__(16) __nv_bfloat16 g_Nl[S_TOT * DIM];
__device__ __align__(16) __nv_bfloat16 g_QKVh[S_TOT * QKVN];
__device__ __align__(16) __nv_bfloat16 g_QKVl[S_TOT * QKVN];
__device__ __align__(16) __nv_bfloat16 g_Ahp[S_TOT * DIM];
__device__ __align__(16) __nv_bfloat16 g_Alp[S_TOT * DIM];
__device__ __align__(16) __nv_bfloat16 g_Fh[S_TOT * HID];
__device__ __align__(16) __nv_bfloat16 g_Fl[S_TOT * HID];

// preconverted weights (hi/lo bf16), all layers
#define WSZ_P   (NLAYER * DIM * DIM)
#define WSZ_FF  (NLAYER * HID * DIM)
#define OFF_QKV 0
#define OFF_WO  (OFF_QKV + 3 * WSZ_P)
#define OFF_W1  (OFF_WO + WSZ_P)
#define OFF_W2  (OFF_W1 + WSZ_FF)
#define WTOT    (OFF_W2 + WSZ_FF)
__device__ __align__(16) __nv_bfloat16 g_Wh[WTOT];
__device__ __align__(16) __nv_bfloat16 g_Wl[WTOT];

// =================== helpers ================================================
__device__ __forceinline__ uint32_t smem_u32(const void* p) {
    uint32_t a;
    asm("{ .reg .u64 t; cvta.to.shared.u64 t, %1; cvt.u32.u64 %0, t; }"
        : "=r"(a) : "l"(p));
    return a;
}
__device__ __forceinline__ void ldsm_x4(uint32_t* r, uint32_t addr) {
    asm volatile("ldmatrix.sync.aligned.m8n8.x4.shared.b16 {%0,%1,%2,%3}, [%4];"
                 : "=r"(r[0]), "=r"(r[1]), "=r"(r[2]), "=r"(r[3]) : "r"(addr));
}
__device__ __forceinline__ void ldsm_x4t(uint32_t* r, uint32_t addr) {
    asm volatile("ldmatrix.sync.aligned.m8n8.x4.trans.shared.b16 {%0,%1,%2,%3}, [%4];"
                 : "=r"(r[0]), "=r"(r[1]), "=r"(r[2]), "=r"(r[3]) : "r"(addr));
}
__device__ __forceinline__ void mma16816(float* c, const uint32_t* a,
                                         const uint32_t b0, const uint32_t b1) {
    asm volatile("mma.sync.aligned.m16n8k16.row.col.f32.bf16.bf16.f32 "
                 "{%0,%1,%2,%3}, {%4,%5,%6,%7}, {%8,%9}, {%0,%1,%2,%3};"
                 : "+f"(c[0]), "+f"(c[1]), "+f"(c[2]), "+f"(c[3])
                 : "r"(a[0]), "r"(a[1]), "r"(a[2]), "r"(a[3]), "r"(b0), "r"(b1));
}
__device__ __forceinline__ void cp_async16(uint32_t dst, const void* src, bool pred) {
    int sz = pred ? 16 : 0;
    asm volatile("cp.async.cg.shared.global [%0], [%1], 16, %2;"
                 :: "r"(dst), "l"(src), "r"(sz) : "memory");
}
#define CP_COMMIT() asm volatile("cp.async.commit_group;" ::: "memory")
#define CP_WAIT1()  asm volatile("cp.async.wait_group 1;" ::: "memory")
#define CP_WAIT0()  asm volatile("cp.async.wait_group 0;" ::: "memory")

// XOR chunk swizzle: 64B rows, 4 chunks of 16B; conflict-free for ldmatrix.
__device__ __forceinline__ uint32_t swz(int row, int chunk) {
    return (uint32_t)(row * 64 + ((chunk ^ ((row >> 1) & 3)) << 4));
}

__device__ __forceinline__ void split4(float4 v, uint2& hi, uint2& lo)
{
    __nv_bfloat16 h0 = __float2bfloat16(v.x);
    __nv_bfloat16 h1 = __float2bfloat16(v.y);
    __nv_bfloat16 h2 = __float2bfloat16(v.z);
    __nv_bfloat16 h3 = __float2bfloat16(v.w);
    __nv_bfloat16 l0 = __float2bfloat16(v.x - __bfloat162float(h0));
    __nv_bfloat16 l1 = __float2bfloat16(v.y - __bfloat162float(h1));
    __nv_bfloat16 l2 = __float2bfloat16(v.z - __bfloat162float(h2));
    __nv_bfloat16 l3 = __float2bfloat16(v.w - __bfloat162float(h3));
    hi.x = (uint32_t)__bfloat16_as_ushort(h1) << 16 | __bfloat16_as_ushort(h0);
    hi.y = (uint32_t)__bfloat16_as_ushort(h3) << 16 | __bfloat16_as_ushort(h2);
    lo.x = (uint32_t)__bfloat16_as_ushort(l1) << 16 | __bfloat16_as_ushort(l0);
    lo.y = (uint32_t)__bfloat16_as_ushort(l3) << 16 | __bfloat16_as_ushort(l2);
}
__device__ __forceinline__ void split2(float a, float b, uint32_t& hi, uint32_t& lo)
{
    __nv_bfloat16 ha = __float2bfloat16(a), hb = __float2bfloat16(b);
    __nv_bfloat16 la = __float2bfloat16(a - __bfloat162float(ha));
    __nv_bfloat16 lb = __float2bfloat16(b - __bfloat162float(hb));
    hi = (uint32_t)__bfloat16_as_ushort(hb) << 16 | __bfloat16_as_ushort(ha);
    lo = (uint32_t)__bfloat16_as_ushort(lb) << 16 | __bfloat16_as_ushort(la);
}

// ---------------- unified weight pre-conversion (1 launch) ------------------
#define N4_QKV (3 * WSZ_P / 4)
#define N4_WO  (WSZ_P / 4)
#define N4_FF  (WSZ_FF / 4)
#define N4_TOT (N4_QKV + N4_WO + 2 * N4_FF)

__global__ void conv_all(const float* __restrict__ wq, const float* __restrict__ wk,
                         const float* __restrict__ wv, const float* __restrict__ wo,
                         const float* __restrict__ w1, const float* __restrict__ w2,
                         __nv_bfloat16* __restrict__ Wh, __nv_bfloat16* __restrict__ Wl)
{
    int i = blockIdx.x * 256 + threadIdx.x;
    if (i >= N4_TOT) return;
    const float* src;
    size_t se, de;
    if (i < N4_QKV) {
        const int n4l = DIM * DIM / 4;
        const int per_t = NLAYER * n4l;
        int t = i / per_t;
        int r = i - t * per_t;
        int l = r / n4l, e = r - l * n4l;
        src = (t == 0) ? wq : (t == 1) ? wk : wv;
        se = (size_t)l * n4l + e;
        de = (size_t)(OFF_QKV / 4) + (size_t)l * (3 * n4l) + (size_t)t * n4l + e;
    } else if (i < N4_QKV + N4_WO) {
        int e = i - N4_QKV;
        src = wo; se = e; de = OFF_WO / 4 + e;
    } else if (i < N4_QKV + N4_WO + N4_FF) {
        int e = i - N4_QKV - N4_WO;
        src = w1; se = e; de = OFF_W1 / 4 + e;
    } else {
        int e = i - N4_QKV - N4_WO - N4_FF;
        src = w2; se = e; de = OFF_W2 / 4 + e;
    }
    float4 v = ((const float4*)src)[se];
    uint2 hi, lo;
    split4(v, hi, lo);
    ((uint2*)Wh)[de] = hi;
    ((uint2*)Wl)[de] = lo;
}

// ---------------- embedding ------------------------------------------------
__global__ void embed_kernel(const int* __restrict__ tokens,
                             const float* __restrict__ emb,
                             const float* __restrict__ pos,
                             const float* __restrict__ mem,
                             float* __restrict__ X)
{
    int idx = blockIdx.x * 256 + threadIdx.x;
    if (idx >= S_TOT * DIM) return;
    int s = idx / DIM;
    int d = idx - s * DIM;
    if (s < MEMN) {
        X[idx] = mem[s * DIM + d];
    } else {
        int t = s - MEMN;
        X[idx] = emb[tokens[t] * DIM + d] + pos[t * DIM + d];
    }
}

// ---------------- layernorm (384 threads, float2 per thread) ----------------
__device__ __forceinline__ void ln_stats384(float a, float b, float& mean, float& inv)
{
    int t = threadIdx.x;
    float s = a + b;
    float q = a * a + b * b;
#pragma unroll
    for (int off = 16; off; off >>= 1) {
        s += __shfl_xor_sync(0xffffffffu, s, off);
        q += __shfl_xor_sync(0xffffffffu, q, off);
    }
    __shared__ float rs[12], rq[12];
    __shared__ float mean_sh, inv_sh;
    int w = t >> 5;
    if ((t & 31) == 0) { rs[w] = s; rq[w] = q; }
    __syncthreads();
    if (t == 0) {
        float S = 0.f, Q = 0.f;
#pragma unroll
        for (int i = 0; i < 12; i++) { S += rs[i]; Q += rq[i]; }
        float mn = S * (1.0f / DIM);
        float var = Q * (1.0f / DIM) - mn * mn;
        mean_sh = mn;
        inv_sh  = rsqrtf(var + 1e-5f);
    }
    __syncthreads();
    mean = mean_sh;
    inv  = inv_sh;
}

__global__ void ln_hl_kernel(const float* __restrict__ X,
                             const float* __restrict__ g,
                             const float* __restrict__ bt,
                             __nv_bfloat16* __restrict__ oh,
                             __nv_bfloat16* __restrict__ ol)
{
    int row = blockIdx.x;
    int t = threadIdx.x;
    float2 v = ((const float2*)(X + (size_t)row * DIM))[t];
    float mean, inv;
    ln_stats384(v.x, v.y, mean, inv);
    float2 gv = ((const float2*)g)[t];
    float2 bv = ((const float2*)bt)[t];
    float y0 = (v.x - mean) * inv * gv.x + bv.x;
    float y1 = (v.y - mean) * inv * gv.y + bv.y;
    uint32_t hi, lo;
    split2(y0, y1, hi, lo);
    ((uint32_t*)oh)[(size_t)row * (DIM / 2) + t] = hi;
    ((uint32_t*)ol)[(size_t)row * (DIM / 2) + t] = lo;
}

__global__ void ln_kernel(const float* __restrict__ X,
                          const float* __restrict__ g,
                          const float* __restrict__ bt,
                          float* __restrict__ out, int in_off)
{
    int row = blockIdx.x + in_off;
    int t = threadIdx.x;
    float2 v = ((const float2*)(X + (size_t)row * DIM))[t];
    float mean, inv;
    ln_stats384(v.x, v.y, mean, inv);
    float2 gv = ((const float2*)g)[t];
    float2 bv = ((const float2*)bt)[t];
    float y0 = (v.x - mean) * inv * gv.x + bv.x;
    float y1 = (v.y - mean) * inv * gv.y + bv.y;
    ((float2*)(out + (size_t)blockIdx.x * DIM))[t] = make_float2(y0, y1);
}

__device__ __forceinline__ float gelu_tanh(float x)
{
    const float c = 0.7978845608028654f;
    float u = c * (x + 0.044715f * x * x * x);
    return 0.5f * x * (1.0f + tanhf(u));
}

// =================== bf16x3 GEMM, CTA 64x128, 3-stage swizzled, 2 CTAs/SM ===
#define BMATB  8192                  // B: 128 rows x 64B
#define GBM    64

struct GemmDims {
    static const int AMATB = GBM * 64;                // A: 64 rows x 64B
    static const int STG   = 2 * AMATB + 2 * BMATB;
    static const int SMEM  = 3 * STG;                 // 73728
    static const int MT    = GBM / 32;                // 2
};

template <bool GELU, bool RES, bool BIAS, bool OUTHL>
__global__ __launch_bounds__(256, 2)
void gemm_tc(const __nv_bfloat16* __restrict__ Ah, const __nv_bfloat16* __restrict__ Al,
             const __nv_bfloat16* __restrict__ Bh, const __nv_bfloat16* __restrict__ Bl,
             const float* __restrict__ bias, const float* __restrict__ resid,
             float* __restrict__ C,
             __nv_bfloat16* __restrict__ Oh, __nv_bfloat16* __restrict__ Ol,
             int Mr, int N, int K)
{
    typedef GemmDims D;
    extern __shared__ char smem[];
    const uint32_t sb = smem_u32(smem);
    const int tid = threadIdx.x, wid = tid >> 5, lane = tid & 31;
    const int bm = blockIdx.y, bn = blockIdx.x;
    const int wm = (wid >> 2) * (GBM / 2);
    const int wn = (wid & 3) * 32;
    const int KT = K >> 5;

    float acc[D::MT][4][4];
#pragma unroll
    for (int i = 0; i < D::MT; i++)
#pragma unroll
        for (int j = 0; j < 4; j++)
#pragma unroll
            for (int k = 0; k < 4; k++) acc[i][j][k] = 0.f;

    auto issue = [&](int kt) {
        const uint32_t stg = sb + (kt % 3) * D::STG;
        const int kb = kt * 32;
        {
            int e = tid;
            int row = e >> 2, kc = e & 3;
            uint32_t d = stg + swz(row, kc);
            int ga = bm * GBM + row;
            const bool av = ga < Mr;
            if (!av) ga = 0;
            const size_t aoff = (size_t)ga * K + kb + kc * 8;
            cp_async16(d,            Ah + aoff, av);
            cp_async16(d + D::AMATB, Al + aoff, av);
        }
#pragma unroll
        for (int i = 0; i < 2; i++) {
            int e = tid + i * 256;
            int row = e >> 2, kc = e & 3;
            uint32_t d = stg + 2 * D::AMATB + swz(row, kc);
            const size_t boff = (size_t)(bn * 128 + row) * K + kb + kc * 8;
            cp_async16(d,         Bh + boff, true);
            cp_async16(d + BMATB, Bl + boff, true);
        }
        CP_COMMIT();
    };

    issue(0);
    if (KT > 1) issue(1);

    const int arow = wm + (lane & 15);
    const int acO  = (lane >> 4) << 3;
    const int brow = wn + (lane & 7) + ((lane >> 4) << 3);
    const int bcO  = ((lane >> 3) & 1) << 3;

    for (int kt = 0; kt < KT; kt++) {
        CP_WAIT1();
        __syncthreads();
        if (kt + 2 < KT) issue(kt + 2);

        const uint32_t base = sb + (kt % 3) * D::STG;
#pragma unroll
        for (int ks = 0; ks < 2; ks++) {
            const int k0 = ks * 16;
            uint32_t aH[D::MT][4], aL[D::MT][4], bH[2][4], bL[2][4];
#pragma unroll
            for (int mt = 0; mt < D::MT; mt++) {
                const int r = arow + mt * 16;
                uint32_t ad = base + swz(r, (k0 + acO) >> 3);
                ldsm_x4(aH[mt], ad);
                ldsm_x4(aL[mt], ad + D::AMATB);
            }
#pragma unroll
            for (int n2 = 0; n2 < 2; n2++) {
                const int r = brow + n2 * 16;
                uint32_t bd = base + 2 * D::AMATB + swz(r, (k0 + bcO) >> 3);
                ldsm_x4(bH[n2], bd);
                ldsm_x4(bL[n2], bd + BMATB);
            }
#pragma unroll
            for (int mt = 0; mt < D::MT; mt++)
#pragma unroll
                for (int nt = 0; nt < 4; nt++) {
                    const int n2 = nt >> 1, hb = (nt & 1) * 2;
                    mma16816(acc[mt][nt], aH[mt], bH[n2][hb], bH[n2][hb + 1]);
                }
#pragma unroll
            for (int mt = 0; mt < D::MT; mt++)
#pragma unroll
                for (int nt = 0; nt < 4; nt++) {
                    const int n2 = nt >> 1, hb = (nt & 1) * 2;
                    mma16816(acc[mt][nt], aH[mt], bL[n2][hb], bL[n2][hb + 1]);
                }
#pragma unroll
            for (int mt = 0; mt < D::MT; mt++)
#pragma unroll
                for (int nt = 0; nt < 4; nt++) {
                    const int n2 = nt >> 1, hb = (nt & 1) * 2;
                    mma16816(acc[mt][nt], aL[mt], bH[n2][hb], bH[n2][hb + 1]);
                }
        }
    }

#pragma unroll
    for (int mt = 0; mt < D::MT; mt++) {
        const int r0 = bm * GBM + wm + mt * 16 + (lane >> 2);
#pragma unroll
        for (int nt = 0; nt < 4; nt++) {
            const int col = bn * 128 + wn + nt * 8 + (lane & 3) * 2;
            float* c = acc[mt][nt];
            float bx = 0.f, by = 0.f;
            if (BIAS) { float2 bv = *(const float2*)(bias + col); bx = bv.x; by = bv.y; }
#pragma unroll
            for (int hh = 0; hh < 2; hh++) {
                const int r = r0 + hh * 8;
                if (r >= Mr) continue;
                float v0 = c[hh * 2 + 0], v1 = c[hh * 2 + 1];
                if (BIAS) { v0 += bx; v1 += by; }
                if (GELU) { v0 = gelu_tanh(v0); v1 = gelu_tanh(v1); }
                if (OUTHL) {
                    uint32_t hi, lo;
                    split2(v0, v1, hi, lo);
                    *(uint32_t*)(Oh + (size_t)r * N + col) = hi;
                    *(uint32_t*)(Ol + (size_t)r * N + col) = lo;
                } else {
                    if (RES) {
                        float2 rv = *(const float2*)(resid + (size_t)r * N + col);
                        v0 += rv.x; v1 += rv.y;
                    }
                    *(float2*)(C + (size_t)r * N + col) = make_float2(v0, v1);
                }
            }
        }
    }
}

// =================== tensor-core flash attention (R10 + interleaved MMA) ====
#define APITCH 72
#define AMATB_A 9216
#define ATTN_SMEM (10 * AMATB_A)

__global__ __launch_bounds__(128)
void attn_tc(const __nv_bfloat16* __restrict__ QKVh,
             const __nv_bfloat16* __restrict__ QKVl,
             __nv_bfloat16* __restrict__ Oh, __nv_bfloat16* __restrict__ Ol)
{
    extern __shared__ char asmem[];
    const uint32_t sb = smem_u32(asmem);
    const uint32_t oQh = 0, oQl = AMATB_A;
    const int qb = gridDim.x - 1 - blockIdx.x;    // heavy blocks first
    const int h = blockIdx.y;
    const int tid = threadIdx.x, wid = tid >> 5, lane = tid & 31;
    const int wr = wid * 16;

#pragma unroll
    for (int i = 0; i < 4; i++) {
        int idx = tid + i * 128;
        int row = idx >> 3, ch = idx & 7;
        size_t goff = (size_t)(qb * 64 + row) * QKVN + h * HD + ch * 8;
        uint32_t soff = row * (APITCH * 2) + ch * 16;
        cp_async16(sb + oQh + soff, QKVh + goff, true);
        cp_async16(sb + oQl + soff, QKVl + goff, true);
    }
    CP_COMMIT();

    auto issueKV = [&](int kb) {
        const uint32_t st = sb + 2 * AMATB_A + (kb & 1) * (4 * AMATB_A);
#pragma unroll
        for (int i = 0; i < 4; i++) {
            int idx = tid + i * 128;
            int row = idx >> 3, ch = idx & 7;
            size_t gK = (size_t)(kb * 64 + row) * QKVN + DIM + h * HD + ch * 8;
            size_t gV = (size_t)(kb * 64 + row) * QKVN + 2 * DIM + h * HD + ch * 8;
            uint32_t soff = row * (APITCH * 2) + ch * 16;
            cp_async16(st + soff,               QKVh + gK, true);
            cp_async16(st + AMATB_A + soff,     QKVl + gK, true);
            cp_async16(st + 2 * AMATB_A + soff, QKVh + gV, true);
            cp_async16(st + 3 * AMATB_A + soff, QKVl + gV, true);
        }
        CP_COMMIT();
    };

    issueKV(0);
    if (qb >= 1) issueKV(1);

    float m_[2] = {-1e30f, -1e30f}, l_[2] = {0.f, 0.f};
    float ov[8][4];
#pragma unroll
    for (int i = 0; i < 8; i++)
#pragma unroll
        for (int j = 0; j < 4; j++) ov[i][j] = 0.f;
    const float scale = 0.125f;

    const int ar = wr + (lane & 15);
    const int ac = (lane >> 4) << 3;
    const int br = (lane & 7) + ((lane >> 4) << 3);
    const int bc = ((lane >> 3) & 1) << 3;
    const int vrb = (lane & 7) + (((lane >> 3) & 1) << 3);
    const int vcb = (lane >> 4) << 3;
    const int lr0 = lane >> 2;
    const int lc0 = (lane & 3) * 2;

    for (int kb = 0; kb <= qb; kb++) {
        if (kb + 1 <= qb) { CP_WAIT1(); } else { CP_WAIT0(); }
        __syncthreads();

        const uint32_t st  = sb + 2 * AMATB_A + (kb & 1) * (4 * AMATB_A);
        const uint32_t oKh = st, oKl = st + AMATB_A;
        const uint32_t oVh = st + 2 * AMATB_A, oVl = st + 3 * AMATB_A;

        float sv[8][4];
#pragma unroll
        for (int i = 0; i < 8; i++)
#pragma unroll
            for (int j = 0; j < 4; j++) sv[i][j] = 0.f;

#pragma unroll
        for (int ks = 0; ks < 4; ks++) {
            uint32_t aH[4], aL[4];
            uint32_t ao = sb + (ar * APITCH + ks * 16 + ac) * 2;
            ldsm_x4(aH, ao + oQh);
            ldsm_x4(aL, ao + oQl);
#pragma unroll
            for (int g = 0; g < 4; g++) {
                uint32_t bH4[4], bL4[4];
                uint32_t bo = ((g * 16 + br) * APITCH + ks * 16 + bc) * 2;
                ldsm_x4(bH4, bo + oKh);
                ldsm_x4(bL4, bo + oKl);
                mma16816(sv[2 * g],     aH, bH4[0], bH4[1]);
                mma16816(sv[2 * g + 1], aH, bH4[2], bH4[3]);
                mma16816(sv[2 * g],     aH, bL4[0], bL4[1]);
                mma16816(sv[2 * g + 1], aH, bL4[2], bL4[3]);
                mma16816(sv[2 * g],     aL, bH4[0], bH4[1]);
                mma16816(sv[2 * g + 1], aL, bH4[2], bH4[3]);
            }
        }

#pragma unroll
        for (int nt = 0; nt < 8; nt++)
#pragma unroll
            for (int e = 0; e < 4; e++) {
                float x = sv[nt][e] * scale;
                if (kb == qb) {
                    int kcol = nt * 8 + lc0 + (e & 1);
                    int qrow = wr + lr0 + ((e >> 1) << 3);
                    if (kcol > qrow) x = -1e30f;
                }
                sv[nt][e] = x;
            }

        float mx0 = -1e30f, mx1 = -1e30f;
#pragma unroll
        for (int nt = 0; nt < 8; nt++) {
            mx0 = fmaxf(mx0, fmaxf(sv[nt][0], sv[nt][1]));
            mx1 = fmaxf(mx1, fmaxf(sv[nt][2], sv[nt][3]));
        }
        mx0 = fmaxf(mx0, __shfl_xor_sync(0xffffffffu, mx0, 1));
        mx0 = fmaxf(mx0, __shfl_xor_sync(0xffffffffu, mx0, 2));
        mx1 = fmaxf(mx1, __shfl_xor_sync(0xffffffffu, mx1, 1));
        mx1 = fmaxf(mx1, __shfl_xor_sync(0xffffffffu, mx1, 2));
        float mn0 = fmaxf(m_[0], mx0), mn1 = fmaxf(m_[1], mx1);
        float cr0 = __expf(m_[0] - mn0), cr1 = __expf(m_[1] - mn1);
        float sum0 = 0.f, sum1 = 0.f;
#pragma unroll
        for (int nt = 0; nt < 8; nt++) {
            float p0 = __expf(sv[nt][0] - mn0);
            float p1 = __expf(sv[nt][1] - mn0);
            float p2 = __expf(sv[nt][2] - mn1);
            float p3 = __expf(sv[nt][3] - mn1);
            sv[nt][0] = p0; sv[nt][1] = p1; sv[nt][2] = p2; sv[nt][3] = p3;
            sum0 += p0 + p1;
            sum1 += p2 + p3;
        }
        sum0 += __shfl_xor_sync(0xffffffffu, sum0, 1);
        sum0 += __shfl_xor_sync(0xffffffffu, sum0, 2);
        sum1 += __shfl_xor_sync(0xffffffffu, sum1, 1);
        sum1 += __shfl_xor_sync(0xffffffffu, sum1, 2);
        l_[0] = l_[0] * cr0 + sum0;
        l_[1] = l_[1] * cr1 + sum1;
        m_[0] = mn0; m_[1] = mn1;
#pragma unroll
        for (int nt = 0; nt < 8; nt++) {
            ov[nt][0] *= cr0; ov[nt][1] *= cr0;
            ov[nt][2] *= cr1; ov[nt][3] *= cr1;
        }

#pragma unroll
        for (int s = 0; s < 4; s++) {
            uint32_t pH[4], pL[4];
            split2(sv[2 * s][0],     sv[2 * s][1],     pH[0], pL[0]);
            split2(sv[2 * s][2],     sv[2 * s][3],     pH[1], pL[1]);
            split2(sv[2 * s + 1][0], sv[2 * s + 1][1], pH[2], pL[2]);
            split2(sv[2 * s + 1][2], sv[2 * s + 1][3], pH[3], pL[3]);
            const int vrow = s * 16 + vrb;
#pragma unroll
            for (int g = 0; g < 4; g++) {
                uint32_t vH4[4], vL4[4];
                uint32_t vo = (vrow * APITCH + g * 16 + vcb) * 2;
                ldsm_x4t(vH4, vo + oVh);
                ldsm_x4t(vL4, vo + oVl);
                mma16816(ov[2 * g],     pH, vH4[0], vH4[1]);
                mma16816(ov[2 * g + 1], pH, vH4[2], vH4[3]);
                mma16816(ov[2 * g],     pH, vL4[0], vL4[1]);
                mma16816(ov[2 * g + 1], pH, vL4[2], vL4[3]);
                mma16816(ov[2 * g],     pL, vH4[0], vH4[1]);
                mma16816(ov[2 * g + 1], pL, vH4[2], vH4[3]);
            }
        }

        __syncthreads();
        if (kb + 2 <= qb) issueKV(kb + 2);
    }

    const float inv0 = 1.0f / l_[0], inv1 = 1.0f / l_[1];
    const int gr0 = qb * 64 + wr + (lane >> 2);
    const int cb  = h * HD + (lane & 3) * 2;
#pragma unroll
    for (int nt = 0; nt < 8; nt++) {
        const int col = cb + nt * 8;
        uint32_t hi, lo;
        split2(ov[nt][0] * inv0, ov[nt][1] * inv0, hi, lo);
        *(uint32_t*)(Oh + (size_t)gr0 * DIM + col) = hi;
        *(uint32_t*)(Ol + (size_t)gr0 * DIM + col) = lo;
        split2(ov[nt][2] * inv1, ov[nt][3] * inv1, hi, lo);
        *(uint32_t*)(Oh + (size_t)(gr0 + 8) * DIM + col) = hi;
        *(uint32_t*)(Ol + (size_t)(gr0 + 8) * DIM + col) = lo;
    }
}

// ---------------- launch ----------------------------------------------------
extern "C" void kernel_launch(void* const* d_in, const int* in_sizes, int n_in,
                              void* d_out, int out_size)
{
    const int*   tokens = (const int*)  d_in[0];
    const float* emb    = (const float*)d_in[1];
    const float* pos    = (const float*)d_in[2];
    const float* mem    = (const float*)d_in[3];
    const float* ln1_s  = (const float*)d_in[4];
    const float* ln1_b  = (const float*)d_in[5];
    const float* wq     = (const float*)d_in[6];
    const float* wk     = (const float*)d_in[7];
    const float* wv     = (const float*)d_in[8];
    const float* wo     = (const float*)d_in[9];
    const float* ln2_s  = (const float*)d_in[10];
    const float* ln2_b  = (const float*)d_in[11];
    const float* w1     = (const float*)d_in[12];
    const float* b1     = (const float*)d_in[13];
    const float* w2     = (const float*)d_in[14];
    const float* b2     = (const float*)d_in[15];
    const float* lnm_s  = (const float*)d_in[16];
    const float* lnm_b  = (const float*)d_in[17];

    float *X;
    __nv_bfloat16 *Nh, *Nl, *QKVh, *QKVl, *Aoh, *Aol, *Fh, *Fl, *Wh, *Wl;
    cudaGetSymbolAddress((void**)&X,    g_X);
    cudaGetSymbolAddress((void**)&Nh,   g_Nh);
    cudaGetSymbolAddress((void**)&Nl,   g_Nl);
    cudaGetSymbolAddress((void**)&QKVh, g_QKVh);
    cudaGetSymbolAddress((void**)&QKVl, g_QKVl);
    cudaGetSymbolAddress((void**)&Aoh,  g_Ahp);
    cudaGetSymbolAddress((void**)&Aol,  g_Alp);
    cudaGetSymbolAddress((void**)&Fh,   g_Fh);
    cudaGetSymbolAddress((void**)&Fl,   g_Fl);
    cudaGetSymbolAddress((void**)&Wh,   g_Wh);
    cudaGetSymbolAddress((void**)&Wl,   g_Wl);

    const int SMEM64 = GemmDims::SMEM;    // 73728

    cudaFuncSetAttribute(attn_tc, cudaFuncAttributeMaxDynamicSharedMemorySize, ATTN_SMEM);
    cudaFuncSetAttribute(gemm_tc<false, false, false, true >, cudaFuncAttributeMaxDynamicSharedMemorySize, SMEM64);
    cudaFuncSetAttribute(gemm_tc<true,  false, true,  true >, cudaFuncAttributeMaxDynamicSharedMemorySize, SMEM64);
    cudaFuncSetAttribute(gemm_tc<false, true,  false, false>, cudaFuncAttributeMaxDynamicSharedMemorySize, SMEM64);
    cudaFuncSetAttribute(gemm_tc<false, true,  true,  false>, cudaFuncAttributeMaxDynamicSharedMemorySize, SMEM64);

    conv_all<<<(N4_TOT + 255) / 256, 256>>>(wq, wk, wv, wo, w1, w2, Wh, Wl);
    embed_kernel<<<(S_TOT * DIM + 255) / 256, 256>>>(tokens, emb, pos, mem, X);

    const int NBM = S_TOT / 64;                       // 33
    const dim3 gQKV(QKVN / 128, NBM);                 // (18, 33)
    const dim3 gFF1 (HID / 128, NBM);                 // (24, 33)
    const dim3 gP64 (DIM / 128, NBM);                 // (6, 33)

    for (int l = 0; l < NLAYER; l++) {
        ln_hl_kernel<<<S_TOT, 384>>>(X, ln1_s + l * DIM, ln1_b + l * DIM, Nh, Nl);

        gemm_tc<false, false, false, true><<<gQKV, 256, SMEM64>>>(
            Nh, Nl,
            Wh + OFF_QKV + (size_t)l * 3 * DIM * DIM, Wl + OFF_QKV + (size_t)l * 3 * DIM * DIM,
            nullptr, nullptr, nullptr, QKVh, QKVl, S_TOT, QKVN, DIM);

        attn_tc<<<dim3(S_TOT / 64, NHEAD), 128, ATTN_SMEM>>>(QKVh, QKVl, Aoh, Aol);

        gemm_tc<false, true, false, false><<<gP64, 256, SMEM64>>>(
            Aoh, Aol, Wh + OFF_WO + (size_t)l * DIM * DIM, Wl + OFF_WO + (size_t)l * DIM * DIM,
            nullptr, X, X, nullptr, nullptr, S_TOT, DIM, DIM);

        ln_hl_kernel<<<S_TOT, 384>>>(X, ln2_s + l * DIM, ln2_b + l * DIM, Nh, Nl);

        gemm_tc<true, false, true, true><<<gFF1, 256, SMEM64>>>(
            Nh, Nl, Wh + OFF_W1 + (size_t)l * HID * DIM, Wl + OFF_W1 + (size_t)l * HID * DIM,
            b1 + l * HID, nullptr, nullptr, Fh, Fl, S_TOT, HID, DIM);

        gemm_tc<false, true, true, false><<<gP64, 256, SMEM64>>>(
            Fh, Fl, Wh + OFF_W2 + (size_t)l * DIM * HID, Wl + OFF_W2 + (size_t)l * DIM * HID,
            b2 + l * DIM, X, X, nullptr, nullptr, S_TOT, DIM, HID);
    }

    ln_kernel<<<MEMN, 384>>>(X, lnm_s, lnm_b, (float*)d_out, S_TOT - MEMN);
}

// round 17
// speedup vs baseline: 1.1383x; 1.0729x over previous
#include <cuda_runtime.h>
#include <cuda_bf16.h>
#include <cstdint>

#define S_TOT 2112          // 64 mem + 2048 tokens
#define MEMN  64
#define DIM   768
#define HID   3072
#define NHEAD 12
#define HD    64
#define NLAYER 4
#define QKVN  (3 * DIM)     // 2304

// ---------------- scratch (device globals; no allocation allowed) ----------
__device__ __align__(16) float g_X [S_TOT * DIM];
__device__ __align__(16) float g_P [2 * S_TOT * DIM];   // split-K partials

__device__ __align__(16) __nv_bfloat16 g_Nh[S_TOT * DIM];
__device__ __align__(16) __nv_bfloat16 g_Nl[S_TOT * DIM];
__device__ __align__(16) __nv_bfloat16 g_QKVh[S_TOT * QKVN];
__device__ __align__(16) __nv_bfloat16 g_QKVl[S_TOT * QKVN];
__device__ __align__(16) __nv_bfloat16 g_Ahp[S_TOT * DIM];
__device__ __align__(16) __nv_bfloat16 g_Alp[S_TOT * DIM];
__device__ __align__(16) __nv_bfloat16 g_Fh[S_TOT * HID];
__device__ __align__(16) __nv_bfloat16 g_Fl[S_TOT * HID];

// preconverted weights (hi/lo bf16), all layers
#define WSZ_P   (NLAYER * DIM * DIM)
#define WSZ_FF  (NLAYER * HID * DIM)
#define OFF_QKV 0
#define OFF_WO  (OFF_QKV + 3 * WSZ_P)
#define OFF_W1  (OFF_WO + WSZ_P)
#define OFF_W2  (OFF_W1 + WSZ_FF)
#define WTOT    (OFF_W2 + WSZ_FF)
__device__ __align__(16) __nv_bfloat16 g_Wh[WTOT];
__device__ __align__(16) __nv_bfloat16 g_Wl[WTOT];

// =================== helpers ================================================
__device__ __forceinline__ uint32_t smem_u32(const void* p) {
    uint32_t a;
    asm("{ .reg .u64 t; cvta.to.shared.u64 t, %1; cvt.u32.u64 %0, t; }"
        : "=r"(a) : "l"(p));
    return a;
}
__device__ __forceinline__ void ldsm_x4(uint32_t* r, uint32_t addr) {
    asm volatile("ldmatrix.sync.aligned.m8n8.x4.shared.b16 {%0,%1,%2,%3}, [%4];"
                 : "=r"(r[0]), "=r"(r[1]), "=r"(r[2]), "=r"(r[3]) : "r"(addr));
}
__device__ __forceinline__ void ldsm_x4t(uint32_t* r, uint32_t addr) {
    asm volatile("ldmatrix.sync.aligned.m8n8.x4.trans.shared.b16 {%0,%1,%2,%3}, [%4];"
                 : "=r"(r[0]), "=r"(r[1]), "=r"(r[2]), "=r"(r[3]) : "r"(addr));
}
__device__ __forceinline__ void mma16816(float* c, const uint32_t* a,
                                         const uint32_t b0, const uint32_t b1) {
    asm volatile("mma.sync.aligned.m16n8k16.row.col.f32.bf16.bf16.f32 "
                 "{%0,%1,%2,%3}, {%4,%5,%6,%7}, {%8,%9}, {%0,%1,%2,%3};"
                 : "+f"(c[0]), "+f"(c[1]), "+f"(c[2]), "+f"(c[3])
                 : "r"(a[0]), "r"(a[1]), "r"(a[2]), "r"(a[3]), "r"(b0), "r"(b1));
}
__device__ __forceinline__ void cp_async16(uint32_t dst, const void* src, bool pred) {
    int sz = pred ? 16 : 0;
    asm volatile("cp.async.cg.shared.global [%0], [%1], 16, %2;"
                 :: "r"(dst), "l"(src), "r"(sz) : "memory");
}
#define CP_COMMIT() asm volatile("cp.async.commit_group;" ::: "memory")
#define CP_WAIT1()  asm volatile("cp.async.wait_group 1;" ::: "memory")
#define CP_WAIT0()  asm volatile("cp.async.wait_group 0;" ::: "memory")

// XOR chunk swizzle: 64B rows, 4 chunks of 16B; conflict-free for ldmatrix.
__device__ __forceinline__ uint32_t swz(int row, int chunk) {
    return (uint32_t)(row * 64 + ((chunk ^ ((row >> 1) & 3)) << 4));
}

__device__ __forceinline__ void split4(float4 v, uint2& hi, uint2& lo)
{
    __nv_bfloat16 h0 = __float2bfloat16(v.x);
    __nv_bfloat16 h1 = __float2bfloat16(v.y);
    __nv_bfloat16 h2 = __float2bfloat16(v.z);
    __nv_bfloat16 h3 = __float2bfloat16(v.w);
    __nv_bfloat16 l0 = __float2bfloat16(v.x - __bfloat162float(h0));
    __nv_bfloat16 l1 = __float2bfloat16(v.y - __bfloat162float(h1));
    __nv_bfloat16 l2 = __float2bfloat16(v.z - __bfloat162float(h2));
    __nv_bfloat16 l3 = __float2bfloat16(v.w - __bfloat162float(h3));
    hi.x = (uint32_t)__bfloat16_as_ushort(h1) << 16 | __bfloat16_as_ushort(h0);
    hi.y = (uint32_t)__bfloat16_as_ushort(h3) << 16 | __bfloat16_as_ushort(h2);
    lo.x = (uint32_t)__bfloat16_as_ushort(l1) << 16 | __bfloat16_as_ushort(l0);
    lo.y = (uint32_t)__bfloat16_as_ushort(l3) << 16 | __bfloat16_as_ushort(l2);
}
__device__ __forceinline__ void split2(float a, float b, uint32_t& hi, uint32_t& lo)
{
    __nv_bfloat16 ha = __float2bfloat16(a), hb = __float2bfloat16(b);
    __nv_bfloat16 la = __float2bfloat16(a - __bfloat162float(ha));
    __nv_bfloat16 lb = __float2bfloat16(b - __bfloat162float(hb));
    hi = (uint32_t)__bfloat16_as_ushort(hb) << 16 | __bfloat16_as_ushort(ha);
    lo = (uint32_t)__bfloat16_as_ushort(lb) << 16 | __bfloat16_as_ushort(la);
}

// ---------------- unified weight pre-conversion (1 launch) ------------------
#define N4_QKV (3 * WSZ_P / 4)
#define N4_WO  (WSZ_P / 4)
#define N4_FF  (WSZ_FF / 4)
#define N4_TOT (N4_QKV + N4_WO + 2 * N4_FF)

__global__ void conv_all(const float* __restrict__ wq, const float* __restrict__ wk,
                         const float* __restrict__ wv, const float* __restrict__ wo,
                         const float* __restrict__ w1, const float* __restrict__ w2,
                         __nv_bfloat16* __restrict__ Wh, __nv_bfloat16* __restrict__ Wl)
{
    int i = blockIdx.x * 256 + threadIdx.x;
    if (i >= N4_TOT) return;
    const float* src;
    size_t se, de;
    if (i < N4_QKV) {
        const int n4l = DIM * DIM / 4;
        const int per_t = NLAYER * n4l;
        int t = i / per_t;
        int r = i - t * per_t;
        int l = r / n4l, e = r - l * n4l;
        src = (t == 0) ? wq : (t == 1) ? wk : wv;
        se = (size_t)l * n4l + e;
        de = (size_t)(OFF_QKV / 4) + (size_t)l * (3 * n4l) + (size_t)t * n4l + e;
    } else if (i < N4_QKV + N4_WO) {
        int e = i - N4_QKV;
        src = wo; se = e; de = OFF_WO / 4 + e;
    } else if (i < N4_QKV + N4_WO + N4_FF) {
        int e = i - N4_QKV - N4_WO;
        src = w1; se = e; de = OFF_W1 / 4 + e;
    } else {
        int e = i - N4_QKV - N4_WO - N4_FF;
        src = w2; se = e; de = OFF_W2 / 4 + e;
    }
    float4 v = ((const float4*)src)[se];
    uint2 hi, lo;
    split4(v, hi, lo);
    ((uint2*)Wh)[de] = hi;
    ((uint2*)Wl)[de] = lo;
}

// ---------------- embedding ------------------------------------------------
__global__ void embed_kernel(const int* __restrict__ tokens,
                             const float* __restrict__ emb,
                             const float* __restrict__ pos,
                             const float* __restrict__ mem,
                             float* __restrict__ X)
{
    int idx = blockIdx.x * 256 + threadIdx.x;
    if (idx >= S_TOT * DIM) return;
    int s = idx / DIM;
    int d = idx - s * DIM;
    if (s < MEMN) {
        X[idx] = mem[s * DIM + d];
    } else {
        int t = s - MEMN;
        X[idx] = emb[tokens[t] * DIM + d] + pos[t * DIM + d];
    }
}

// ---------------- split-K reduce: X += P0 + P1 (+bias) ----------------------
template <bool BIAS>
__global__ void reduce_k(float* __restrict__ X, const float* __restrict__ P,
                         const float* __restrict__ bias)
{
    int idx = blockIdx.x * 256 + threadIdx.x;       // float2 index
    if (idx >= S_TOT * DIM / 2) return;
    float2 x = ((float2*)X)[idx];
    float2 a = ((const float2*)P)[idx];
    float2 b = ((const float2*)P)[idx + S_TOT * DIM / 2];
    x.x += a.x + b.x;
    x.y += a.y + b.y;
    if (BIAS) {
        int col = (idx * 2) % DIM;
        float2 bv = *(const float2*)(bias + col);
        x.x += bv.x;
        x.y += bv.y;
    }
    ((float2*)X)[idx] = x;
}

// ---------------- layernorm (384 threads, float2 per thread) ----------------
__device__ __forceinline__ void ln_stats384(float a, float b, float& mean, float& inv)
{
    int t = threadIdx.x;
    float s = a + b;
    float q = a * a + b * b;
#pragma unroll
    for (int off = 16; off; off >>= 1) {
        s += __shfl_xor_sync(0xffffffffu, s, off);
        q += __shfl_xor_sync(0xffffffffu, q, off);
    }
    __shared__ float rs[12], rq[12];
    __shared__ float mean_sh, inv_sh;
    int w = t >> 5;
    if ((t & 31) == 0) { rs[w] = s; rq[w] = q; }
    __syncthreads();
    if (t == 0) {
        float S = 0.f, Q = 0.f;
#pragma unroll
        for (int i = 0; i < 12; i++) { S += rs[i]; Q += rq[i]; }
        float mn = S * (1.0f / DIM);
        float var = Q * (1.0f / DIM) - mn * mn;
        mean_sh = mn;
        inv_sh  = rsqrtf(var + 1e-5f);
    }
    __syncthreads();
    mean = mean_sh;
    inv  = inv_sh;
}

__global__ void ln_hl_kernel(const float* __restrict__ X,
                             const float* __restrict__ g,
                             const float* __restrict__ bt,
                             __nv_bfloat16* __restrict__ oh,
                             __nv_bfloat16* __restrict__ ol)
{
    int row = blockIdx.x;
    int t = threadIdx.x;
    float2 v = ((const float2*)(X + (size_t)row * DIM))[t];
    float mean, inv;
    ln_stats384(v.x, v.y, mean, inv);
    float2 gv = ((const float2*)g)[t];
    float2 bv = ((const float2*)bt)[t];
    float y0 = (v.x - mean) * inv * gv.x + bv.x;
    float y1 = (v.y - mean) * inv * gv.y + bv.y;
    uint32_t hi, lo;
    split2(y0, y1, hi, lo);
    ((uint32_t*)oh)[(size_t)row * (DIM / 2) + t] = hi;
    ((uint32_t*)ol)[(size_t)row * (DIM / 2) + t] = lo;
}

__global__ void ln_kernel(const float* __restrict__ X,
                          const float* __restrict__ g,
                          const float* __restrict__ bt,
                          float* __restrict__ out, int in_off)
{
    int row = blockIdx.x + in_off;
    int t = threadIdx.x;
    float2 v = ((const float2*)(X + (size_t)row * DIM))[t];
    float mean, inv;
    ln_stats384(v.x, v.y, mean, inv);
    float2 gv = ((const float2*)g)[t];
    float2 bv = ((const float2*)bt)[t];
    float y0 = (v.x - mean) * inv * gv.x + bv.x;
    float y1 = (v.y - mean) * inv * gv.y + bv.y;
    ((float2*)(out + (size_t)blockIdx.x * DIM))[t] = make_float2(y0, y1);
}

__device__ __forceinline__ float gelu_tanh(float x)
{
    const float c = 0.7978845608028654f;
    float u = c * (x + 0.044715f * x * x * x);
    return 0.5f * x * (1.0f + tanhf(u));
}

// =================== bf16x3 GEMM, CTA 64x128, 3-stage swizzled, 2 CTAs/SM ===
// KSPLIT>1: blockIdx.z selects a K-slice; raw fp32 partials to Pout+z*Mr*N.
#define BMATB  8192                  // B: 128 rows x 64B
#define GBM    64

struct GemmDims {
    static const int AMATB = GBM * 64;
    static const int STG   = 2 * AMATB + 2 * BMATB;
    static const int SMEM  = 3 * STG;                 // 73728
    static const int MT    = GBM / 32;                // 2
};

template <bool GELU, bool BIAS, bool OUTHL, int KSPLIT>
__global__ __launch_bounds__(256, 2)
void gemm_tc(const __nv_bfloat16* __restrict__ Ah, const __nv_bfloat16* __restrict__ Al,
             const __nv_bfloat16* __restrict__ Bh, const __nv_bfloat16* __restrict__ Bl,
             const float* __restrict__ bias,
             float* __restrict__ C,
             __nv_bfloat16* __restrict__ Oh, __nv_bfloat16* __restrict__ Ol,
             int Mr, int N, int K)
{
    typedef GemmDims D;
    extern __shared__ char smem[];
    const uint32_t sb = smem_u32(smem);
    const int tid = threadIdx.x, wid = tid >> 5, lane = tid & 31;
    const int bm = blockIdx.y, bn = blockIdx.x;
    const int wm = (wid >> 2) * (GBM / 2);
    const int wn = (wid & 3) * 32;
    const int kper = K / KSPLIT;
    const int koff = blockIdx.z * kper;
    const int KT = kper >> 5;

    float acc[D::MT][4][4];
#pragma unroll
    for (int i = 0; i < D::MT; i++)
#pragma unroll
        for (int j = 0; j < 4; j++)
#pragma unroll
            for (int k = 0; k < 4; k++) acc[i][j][k] = 0.f;

    auto issue = [&](int kt) {
        const uint32_t stg = sb + (kt % 3) * D::STG;
        const int kb = koff + kt * 32;
        {
            int e = tid;
            int row = e >> 2, kc = e & 3;
            uint32_t d = stg + swz(row, kc);
            int ga = bm * GBM + row;
            const bool av = ga < Mr;
            if (!av) ga = 0;
            const size_t aoff = (size_t)ga * K + kb + kc * 8;
            cp_async16(d,            Ah + aoff, av);
            cp_async16(d + D::AMATB, Al + aoff, av);
        }
#pragma unroll
        for (int i = 0; i < 2; i++) {
            int e = tid + i * 256;
            int row = e >> 2, kc = e & 3;
            uint32_t d = stg + 2 * D::AMATB + swz(row, kc);
            const size_t boff = (size_t)(bn * 128 + row) * K + kb + kc * 8;
            cp_async16(d,         Bh + boff, true);
            cp_async16(d + BMATB, Bl + boff, true);
        }
        CP_COMMIT();
    };

    issue(0);
    if (KT > 1) issue(1);

    const int arow = wm + (lane & 15);
    const int acO  = (lane >> 4) << 3;
    const int brow = wn + (lane & 7) + ((lane >> 4) << 3);
    const int bcO  = ((lane >> 3) & 1) << 3;

    for (int kt = 0; kt < KT; kt++) {
        CP_WAIT1();
        __syncthreads();
        if (kt + 2 < KT) issue(kt + 2);

        const uint32_t base = sb + (kt % 3) * D::STG;
#pragma unroll
        for (int ks = 0; ks < 2; ks++) {
            const int k0 = ks * 16;
            uint32_t aH[D::MT][4], aL[D::MT][4], bH[2][4], bL[2][4];
#pragma unroll
            for (int mt = 0; mt < D::MT; mt++) {
                const int r = arow + mt * 16;
                uint32_t ad = base + swz(r, (k0 + acO) >> 3);
                ldsm_x4(aH[mt], ad);
                ldsm_x4(aL[mt], ad + D::AMATB);
            }
#pragma unroll
            for (int n2 = 0; n2 < 2; n2++) {
                const int r = brow + n2 * 16;
                uint32_t bd = base + 2 * D::AMATB + swz(r, (k0 + bcO) >> 3);
                ldsm_x4(bH[n2], bd);
                ldsm_x4(bL[n2], bd + BMATB);
            }
#pragma unroll
            for (int mt = 0; mt < D::MT; mt++)
#pragma unroll
                for (int nt = 0; nt < 4; nt++) {
                    const int n2 = nt >> 1, hb = (nt & 1) * 2;
                    mma16816(acc[mt][nt], aH[mt], bH[n2][hb], bH[n2][hb + 1]);
                }
#pragma unroll
            for (int mt = 0; mt < D::MT; mt++)
#pragma unroll
                for (int nt = 0; nt < 4; nt++) {
                    const int n2 = nt >> 1, hb = (nt & 1) * 2;
                    mma16816(acc[mt][nt], aH[mt], bL[n2][hb], bL[n2][hb + 1]);
                }
#pragma unroll
            for (int mt = 0; mt < D::MT; mt++)
#pragma unroll
                for (int nt = 0; nt < 4; nt++) {
                    const int n2 = nt >> 1, hb = (nt & 1) * 2;
                    mma16816(acc[mt][nt], aL[mt], bH[n2][hb], bH[n2][hb + 1]);
                }
        }
    }

    float* Cout = C;
    if (KSPLIT > 1) Cout = C + (size_t)blockIdx.z * Mr * N;

#pragma unroll
    for (int mt = 0; mt < D::MT; mt++) {
        const int r0 = bm * GBM + wm + mt * 16 + (lane >> 2);
#pragma unroll
        for (int nt = 0; nt < 4; nt++) {
            const int col = bn * 128 + wn + nt * 8 + (lane & 3) * 2;
            float* c = acc[mt][nt];
            float bx = 0.f, by = 0.f;
            if (BIAS) { float2 bv = *(const float2*)(bias + col); bx = bv.x; by = bv.y; }
#pragma unroll
            for (int hh = 0; hh < 2; hh++) {
                const int r = r0 + hh * 8;
                if (r >= Mr) continue;
                float v0 = c[hh * 2 + 0], v1 = c[hh * 2 + 1];
                if (BIAS) { v0 += bx; v1 += by; }
                if (GELU) { v0 = gelu_tanh(v0); v1 = gelu_tanh(v1); }
                if (OUTHL) {
                    uint32_t hi, lo;
                    split2(v0, v1, hi, lo);
                    *(uint32_t*)(Oh + (size_t)r * N + col) = hi;
                    *(uint32_t*)(Ol + (size_t)r * N + col) = lo;
                } else {
                    *(float2*)(Cout + (size_t)r * N + col) = make_float2(v0, v1);
                }
            }
        }
    }
}

// =================== tensor-core flash attention =============================
#define APITCH 72
#define AMATB_A 9216
#define ATTN_SMEM (10 * AMATB_A)

__global__ __launch_bounds__(128)
void attn_tc(const __nv_bfloat16* __restrict__ QKVh,
             const __nv_bfloat16* __restrict__ QKVl,
             __nv_bfloat16* __restrict__ Oh, __nv_bfloat16* __restrict__ Ol)
{
    extern __shared__ char asmem[];
    const uint32_t sb = smem_u32(asmem);
    const uint32_t oQh = 0, oQl = AMATB_A;
    const int qb = gridDim.x - 1 - blockIdx.x;    // heavy blocks first
    const int h = blockIdx.y;
    const int tid = threadIdx.x, wid = tid >> 5, lane = tid & 31;
    const int wr = wid * 16;

#pragma unroll
    for (int i = 0; i < 4; i++) {
        int idx = tid + i * 128;
        int row = idx >> 3, ch = idx & 7;
        size_t goff = (size_t)(qb * 64 + row) * QKVN + h * HD + ch * 8;
        uint32_t soff = row * (APITCH * 2) + ch * 16;
        cp_async16(sb + oQh + soff, QKVh + goff, true);
        cp_async16(sb + oQl + soff, QKVl + goff, true);
    }
    CP_COMMIT();

    auto issueKV = [&](int kb) {
        const uint32_t st = sb + 2 * AMATB_A + (kb & 1) * (4 * AMATB_A);
#pragma unroll
        for (int i = 0; i < 4; i++) {
            int idx = tid + i * 128;
            int row = idx >> 3, ch = idx & 7;
            size_t gK = (size_t)(kb * 64 + row) * QKVN + DIM + h * HD + ch * 8;
            size_t gV = (size_t)(kb * 64 + row) * QKVN + 2 * DIM + h * HD + ch * 8;
            uint32_t soff = row * (APITCH * 2) + ch * 16;
            cp_async16(st + soff,               QKVh + gK, true);
            cp_async16(st + AMATB_A + soff,     QKVl + gK, true);
            cp_async16(st + 2 * AMATB_A + soff, QKVh + gV, true);
            cp_async16(st + 3 * AMATB_A + soff, QKVl + gV, true);
        }
        CP_COMMIT();
    };

    issueKV(0);
    if (qb >= 1) issueKV(1);

    float m_[2] = {-1e30f, -1e30f}, l_[2] = {0.f, 0.f};
    float ov[8][4];
#pragma unroll
    for (int i = 0; i < 8; i++)
#pragma unroll
        for (int j = 0; j < 4; j++) ov[i][j] = 0.f;
    const float scale = 0.125f;

    const int ar = wr + (lane & 15);
    const int ac = (lane >> 4) << 3;
    const int br = (lane & 7) + ((lane >> 4) << 3);
    const int bc = ((lane >> 3) & 1) << 3;
    const int vrb = (lane & 7) + (((lane >> 3) & 1) << 3);
    const int vcb = (lane >> 4) << 3;
    const int lr0 = lane >> 2;
    const int lc0 = (lane & 3) * 2;

    for (int kb = 0; kb <= qb; kb++) {
        if (kb + 1 <= qb) { CP_WAIT1(); } else { CP_WAIT0(); }
        __syncthreads();

        const uint32_t st  = sb + 2 * AMATB_A + (kb & 1) * (4 * AMATB_A);
        const uint32_t oKh = st, oKl = st + AMATB_A;
        const uint32_t oVh = st + 2 * AMATB_A, oVl = st + 3 * AMATB_A;

        float sv[8][4];
#pragma unroll
        for (int i = 0; i < 8; i++)
#pragma unroll
            for (int j = 0; j < 4; j++) sv[i][j] = 0.f;

#pragma unroll
        for (int ks = 0; ks < 4; ks++) {
            uint32_t aH[4], aL[4];
            uint32_t ao = sb + (ar * APITCH + ks * 16 + ac) * 2;
            ldsm_x4(aH, ao + oQh);
            ldsm_x4(aL, ao + oQl);
#pragma unroll
            for (int g = 0; g < 4; g++) {
                uint32_t bH4[4], bL4[4];
                uint32_t bo = ((g * 16 + br) * APITCH + ks * 16 + bc) * 2;
                ldsm_x4(bH4, bo + oKh);
                ldsm_x4(bL4, bo + oKl);
                mma16816(sv[2 * g],     aH, bH4[0], bH4[1]);
                mma16816(sv[2 * g + 1], aH, bH4[2], bH4[3]);
                mma16816(sv[2 * g],     aH, bL4[0], bL4[1]);
                mma16816(sv[2 * g + 1], aH, bL4[2], bL4[3]);
                mma16816(sv[2 * g],     aL, bH4[0], bH4[1]);
                mma16816(sv[2 * g + 1], aL, bH4[2], bH4[3]);
            }
        }

#pragma unroll
        for (int nt = 0; nt < 8; nt++)
#pragma unroll
            for (int e = 0; e < 4; e++) {
                float x = sv[nt][e] * scale;
                if (kb == qb) {
                    int kcol = nt * 8 + lc0 + (e & 1);
                    int qrow = wr + lr0 + ((e >> 1) << 3);
                    if (kcol > qrow) x = -1e30f;
                }
                sv[nt][e] = x;
            }

        float mx0 = -1e30f, mx1 = -1e30f;
#pragma unroll
        for (int nt = 0; nt < 8; nt++) {
            mx0 = fmaxf(mx0, fmaxf(sv[nt][0], sv[nt][1]));
            mx1 = fmaxf(mx1, fmaxf(sv[nt][2], sv[nt][3]));
        }
        mx0 = fmaxf(mx0, __shfl_xor_sync(0xffffffffu, mx0, 1));
        mx0 = fmaxf(mx0, __shfl_xor_sync(0xffffffffu, mx0, 2));
        mx1 = fmaxf(mx1, __shfl_xor_sync(0xffffffffu, mx1, 1));
        mx1 = fmaxf(mx1, __shfl_xor_sync(0xffffffffu, mx1, 2));
        float mn0 = fmaxf(m_[0], mx0), mn1 = fmaxf(m_[1], mx1);
        float cr0 = __expf(m_[0] - mn0), cr1 = __expf(m_[1] - mn1);
        float sum0 = 0.f, sum1 = 0.f;
#pragma unroll
        for (int nt = 0; nt < 8; nt++) {
            float p0 = __expf(sv[nt][0] - mn0);
            float p1 = __expf(sv[nt][1] - mn0);
            float p2 = __expf(sv[nt][2] - mn1);
            float p3 = __expf(sv[nt][3] - mn1);
            sv[nt][0] = p0; sv[nt][1] = p1; sv[nt][2] = p2; sv[nt][3] = p3;
            sum0 += p0 + p1;
            sum1 += p2 + p3;
        }
        sum0 += __shfl_xor_sync(0xffffffffu, sum0, 1);
        sum0 += __shfl_xor_sync(0xffffffffu, sum0, 2);
        sum1 += __shfl_xor_sync(0xffffffffu, sum1, 1);
        sum1 += __shfl_xor_sync(0xffffffffu, sum1, 2);
        l_[0] = l_[0] * cr0 + sum0;
        l_[1] = l_[1] * cr1 + sum1;
        m_[0] = mn0; m_[1] = mn1;
#pragma unroll
        for (int nt = 0; nt < 8; nt++) {
            ov[nt][0] *= cr0; ov[nt][1] *= cr0;
            ov[nt][2] *= cr1; ov[nt][3] *= cr1;
        }

#pragma unroll
        for (int s = 0; s < 4; s++) {
            uint32_t pH[4], pL[4];
            split2(sv[2 * s][0],     sv[2 * s][1],     pH[0], pL[0]);
            split2(sv[2 * s][2],     sv[2 * s][3],     pH[1], pL[1]);
            split2(sv[2 * s + 1][0], sv[2 * s + 1][1], pH[2], pL[2]);
            split2(sv[2 * s + 1][2], sv[2 * s + 1][3], pH[3], pL[3]);
            const int vrow = s * 16 + vrb;
#pragma unroll
            for (int g = 0; g < 4; g++) {
                uint32_t vH4[4], vL4[4];
                uint32_t vo = (vrow * APITCH + g * 16 + vcb) * 2;
                ldsm_x4t(vH4, vo + oVh);
                ldsm_x4t(vL4, vo + oVl);
                mma16816(ov[2 * g],     pH, vH4[0], vH4[1]);
                mma16816(ov[2 * g + 1], pH, vH4[2], vH4[3]);
                mma16816(ov[2 * g],     pH, vL4[0], vL4[1]);
                mma16816(ov[2 * g + 1], pH, vL4[2], vL4[3]);
                mma16816(ov[2 * g],     pL, vH4[0], vH4[1]);
                mma16816(ov[2 * g + 1], pL, vH4[2], vH4[3]);
            }
        }

        __syncthreads();
        if (kb + 2 <= qb) issueKV(kb + 2);
    }

    const float inv0 = 1.0f / l_[0], inv1 = 1.0f / l_[1];
    const int gr0 = qb * 64 + wr + (lane >> 2);
    const int cb  = h * HD + (lane & 3) * 2;
#pragma unroll
    for (int nt = 0; nt < 8; nt++) {
        const int col = cb + nt * 8;
        uint32_t hi, lo;
        split2(ov[nt][0] * inv0, ov[nt][1] * inv0, hi, lo);
        *(uint32_t*)(Oh + (size_t)gr0 * DIM + col) = hi;
        *(uint32_t*)(Ol + (size_t)gr0 * DIM + col) = lo;
        split2(ov[nt][2] * inv1, ov[nt][3] * inv1, hi, lo);
        *(uint32_t*)(Oh + (size_t)(gr0 + 8) * DIM + col) = hi;
        *(uint32_t*)(Ol + (size_t)(gr0 + 8) * DIM + col) = lo;
    }
}

// ---------------- launch ----------------------------------------------------
extern "C" void kernel_launch(void* const* d_in, const int* in_sizes, int n_in,
                              void* d_out, int out_size)
{
    const int*   tokens = (const int*)  d_in[0];
    const float* emb    = (const float*)d_in[1];
    const float* pos    = (const float*)d_in[2];
    const float* mem    = (const float*)d_in[3];
    const float* ln1_s  = (const float*)d_in[4];
    const float* ln1_b  = (const float*)d_in[5];
    const float* wq     = (const float*)d_in[6];
    const float* wk     = (const float*)d_in[7];
    const float* wv     = (const float*)d_in[8];
    const float* wo     = (const float*)d_in[9];
    const float* ln2_s  = (const float*)d_in[10];
    const float* ln2_b  = (const float*)d_in[11];
    const float* w1     = (const float*)d_in[12];
    const float* b1     = (const float*)d_in[13];
    const float* w2     = (const float*)d_in[14];
    const float* b2     = (const float*)d_in[15];
    const float* lnm_s  = (const float*)d_in[16];
    const float* lnm_b  = (const float*)d_in[17];

    float *X, *P;
    __nv_bfloat16 *Nh, *Nl, *QKVh, *QKVl, *Aoh, *Aol, *Fh, *Fl, *Wh, *Wl;
    cudaGetSymbolAddress((void**)&X,    g_X);
    cudaGetSymbolAddress((void**)&P,    g_P);
    cudaGetSymbolAddress((void**)&Nh,   g_Nh);
    cudaGetSymbolAddress((void**)&Nl,   g_Nl);
    cudaGetSymbolAddress((void**)&QKVh, g_QKVh);
    cudaGetSymbolAddress((void**)&QKVl, g_QKVl);
    cudaGetSymbolAddress((void**)&Aoh,  g_Ahp);
    cudaGetSymbolAddress((void**)&Aol,  g_Alp);
    cudaGetSymbolAddress((void**)&Fh,   g_Fh);
    cudaGetSymbolAddress((void**)&Fl,   g_Fl);
    cudaGetSymbolAddress((void**)&Wh,   g_Wh);
    cudaGetSymbolAddress((void**)&Wl,   g_Wl);

    const int SMEM64 = GemmDims::SMEM;    // 73728

    cudaFuncSetAttribute(attn_tc, cudaFuncAttributeMaxDynamicSharedMemorySize, ATTN_SMEM);
    cudaFuncSetAttribute(gemm_tc<false, false, true,  1>, cudaFuncAttributeMaxDynamicSharedMemorySize, SMEM64);
    cudaFuncSetAttribute(gemm_tc<true,  true,  true,  1>, cudaFuncAttributeMaxDynamicSharedMemorySize, SMEM64);
    cudaFuncSetAttribute(gemm_tc<false, false, false, 2>, cudaFuncAttributeMaxDynamicSharedMemorySize, SMEM64);

    conv_all<<<(N4_TOT + 255) / 256, 256>>>(wq, wk, wv, wo, w1, w2, Wh, Wl);
    embed_kernel<<<(S_TOT * DIM + 255) / 256, 256>>>(tokens, emb, pos, mem, X);

    const int NBM = S_TOT / 64;                       // 33
    const dim3 gQKV(QKVN / 128, NBM);                 // (18, 33)
    const dim3 gFF1 (HID / 128, NBM);                 // (24, 33)
    const dim3 gP2  (DIM / 128, NBM, 2);              // (6, 33, 2) split-K
    const int  RED_GRID = (S_TOT * DIM / 2 + 255) / 256;

    for (int l = 0; l < NLAYER; l++) {
        ln_hl_kernel<<<S_TOT, 384>>>(X, ln1_s + l * DIM, ln1_b + l * DIM, Nh, Nl);

        gemm_tc<false, false, true, 1><<<gQKV, 256, SMEM64>>>(
            Nh, Nl,
            Wh + OFF_QKV + (size_t)l * 3 * DIM * DIM, Wl + OFF_QKV + (size_t)l * 3 * DIM * DIM,
            nullptr, nullptr, QKVh, QKVl, S_TOT, QKVN, DIM);

        attn_tc<<<dim3(S_TOT / 64, NHEAD), 128, ATTN_SMEM>>>(QKVh, QKVl, Aoh, Aol);

        // WO: split-K=2 partials, then X += P0+P1
        gemm_tc<false, false, false, 2><<<gP2, 256, SMEM64>>>(
            Aoh, Aol, Wh + OFF_WO + (size_t)l * DIM * DIM, Wl + OFF_WO + (size_t)l * DIM * DIM,
            nullptr, P, nullptr, nullptr, S_TOT, DIM, DIM);
        reduce_k<false><<<RED_GRID, 256>>>(X, P, nullptr);

        ln_hl_kernel<<<S_TOT, 384>>>(X, ln2_s + l * DIM, ln2_b + l * DIM, Nh, Nl);

        gemm_tc<true, true, true, 1><<<gFF1, 256, SMEM64>>>(
            Nh, Nl, Wh + OFF_W1 + (size_t)l * HID * DIM, Wl + OFF_W1 + (size_t)l * HID * DIM,
            b1 + l * HID, nullptr, Fh, Fl, S_TOT, HID, DIM);

        // FF2: split-K=2 partials, then X += P0+P1+b2
        gemm_tc<false, false, false, 2><<<gP2, 256, SMEM64>>>(
            Fh, Fl, Wh + OFF_W2 + (size_t)l * DIM * HID, Wl + OFF_W2 + (size_t)l * DIM * HID,
            nullptr, P, nullptr, nullptr, S_TOT, DIM, HID);
        reduce_k<true><<<RED_GRID, 256>>>(X, P, b2 + l * DIM);
    }

    ln_kernel<<<MEMN, 384>>>(X, lnm_s, lnm_b, (float*)d_out, S_TOT - MEMN);
}